// round 5
// baseline (speedup 1.0000x reference)
#include <cuda_runtime.h>
#include <cuda_bf16.h>
#include <cstdint>

#define NN 1024
#define BB 32
#define FF 32
#define DD 64
#define HH 64
#define CC 2048   // B*D
#define NP1 1025

// ---------------- scratch (static __device__, no allocs) ----------------
__device__ __nv_bfloat16 g_Abf[NN * NN];    // binarized adjacency, bf16 (exact 0/1)
__device__ float g_m13[NN * CC];            // mu_1 + mu3 + b2
__device__ float g_mu[NN * CC];             // current mu (fp32), [n][b*64+d]
__device__ __nv_bfloat16 g_nu_hi[NN * CC];  // hi part of nu = mu @ W2^T
__device__ __nv_bfloat16 g_nu_lo[NN * CC];  // lo part
__device__ float g_mu3[NN * DD];
__device__ float g_part[16 * CC];           // column-sum partials (one per 64-row mtile)
__device__ float g_mumean[BB * DD];
__device__ float g_s2[BB * HH];

// ---------------- helpers ----------------
__device__ __forceinline__ uint32_t smem_u32(const void* p) {
    uint32_t a;
    asm("{ .reg .u64 t; cvta.to.shared.u64 t, %1; cvt.u32.u64 %0, t; }" : "=r"(a) : "l"(p));
    return a;
}
__device__ __forceinline__ void cp16(uint32_t saddr, const void* gaddr) {
    asm volatile("cp.async.cg.shared.global [%0], [%1], 16;\n" :: "r"(saddr), "l"(gaddr));
}

// ---------------- adjacency: binarize to bf16 + mu3 (one adj read) ----------------
__global__ __launch_bounds__(256) void k_graph(const float* __restrict__ adj,
                                               const float* __restrict__ W4,
                                               const float* __restrict__ b4,
                                               const float* __restrict__ W3,
                                               const float* __restrict__ b3) {
    int n = blockIdx.x;
    int tid = threadIdx.x;
    __shared__ float arow[NN];
    __shared__ float part[4][DD];
    __shared__ float mu4s[DD];

    {
        float4 v = ((const float4*)(adj + (size_t)n * NN))[tid];
        arow[tid * 4 + 0] = v.x;
        arow[tid * 4 + 1] = v.y;
        arow[tid * 4 + 2] = v.z;
        arow[tid * 4 + 3] = v.w;
        union { uint2 u; __nv_bfloat16 h[4]; } pk;
        pk.h[0] = __float2bfloat16(v.x > 0.f ? 1.f : 0.f);
        pk.h[1] = __float2bfloat16(v.y > 0.f ? 1.f : 0.f);
        pk.h[2] = __float2bfloat16(v.z > 0.f ? 1.f : 0.f);
        pk.h[3] = __float2bfloat16(v.w > 0.f ? 1.f : 0.f);
        *(uint2*)(g_Abf + (size_t)n * NN + tid * 4) = pk.u;
    }
    __syncthreads();

    int d = tid & 63, q = tid >> 6;
    float w = W4[d], c0 = b4[d];
    float acc = 0.f;
    for (int m = q; m < NN; m += 4)
        acc += fmaxf(arow[m] * w + c0, 0.f);
    part[q][d] = acc;
    __syncthreads();
    if (tid < DD) mu4s[tid] = part[0][tid] + part[1][tid] + part[2][tid] + part[3][tid];
    __syncthreads();
    if (tid < DD) {
        int d2 = tid;
        float a = b3[d2];
#pragma unroll
        for (int e = 0; e < DD; e++) a += mu4s[e] * W3[d2 * DD + e];
        g_mu3[n * DD + d2] = a;
    }
}

// ---------------- mu_1 + m13 + first nu (fused) ----------------
__global__ __launch_bounds__(256) void k_mu1(const float* __restrict__ xv,
                                             const float* __restrict__ mu1w,
                                             const float* __restrict__ b2,
                                             const float* __restrict__ W2) {
    int n = blockIdx.x;
    __shared__ float xs[BB][FF];
    __shared__ float ws[FF][DD];
    __shared__ float m3[DD];
    __shared__ float mus[CC];
    __shared__ float W2sp[DD * 65];
    int tid = threadIdx.x;
    for (int i = tid; i < BB * FF; i += 256) {
        int b = i / FF, f = i % FF;
        xs[b][f] = xv[(b * NN + n) * FF + f];
    }
    for (int i = tid; i < FF * DD; i += 256) ws[i / DD][i % DD] = mu1w[i];
    for (int i = tid; i < DD * DD; i += 256) W2sp[(i >> 6) * 65 + (i & 63)] = W2[i];
    if (tid < DD) m3[tid] = g_mu3[n * DD + tid] + b2[tid];
    __syncthreads();
#pragma unroll
    for (int j = 0; j < 8; j++) {
        int c = tid + 256 * j;
        int b = c >> 6, d = c & 63;
        float acc = 0.f;
#pragma unroll
        for (int f = 0; f < FF; f++) acc += xs[b][f] * ws[f][d];
        float r = fmaxf(acc, 0.f);
        g_mu[n * CC + c] = r;
        g_m13[n * CC + c] = r + m3[d];
        mus[c] = r;
    }
    __syncthreads();

    int b = tid >> 3, dg = tid & 7;
    float mur[DD];
#pragma unroll
    for (int e4 = 0; e4 < 16; e4++) {
        float4 v = ((const float4*)(mus + b * DD))[e4];
        mur[4 * e4] = v.x; mur[4 * e4 + 1] = v.y; mur[4 * e4 + 2] = v.z; mur[4 * e4 + 3] = v.w;
    }
    union { uint4 u; __nv_bfloat16 h[8]; } ph, pl;
#pragma unroll
    for (int k = 0; k < 8; k++) {
        int d = dg * 8 + k;
        float acc = 0.f;
#pragma unroll
        for (int e = 0; e < DD; e++) acc += mur[e] * W2sp[d * 65 + e];
        __nv_bfloat16 hi = __float2bfloat16(acc);
        ph.h[k] = hi;
        pl.h[k] = __float2bfloat16(acc - __bfloat162float(hi));
    }
    size_t off = (size_t)n * CC + b * DD + dg * 8;
    *(uint4*)(g_nu_hi + off) = ph.u;
    *(uint4*)(g_nu_lo + off) = pl.u;
}

// ---------------- nu = mu @ W2^T, register-blocked, hi/lo bf16 ----------------
__global__ __launch_bounds__(256) void k_nu(const float* __restrict__ W2) {
    int n = blockIdx.x;
    __shared__ float mus[CC];
    __shared__ float W2sp[DD * 65];
    int tid = threadIdx.x;
    for (int i = tid; i < DD * DD; i += 256) W2sp[(i >> 6) * 65 + (i & 63)] = W2[i];
    for (int i = tid; i < CC / 4; i += 256)
        ((float4*)mus)[i] = ((const float4*)(g_mu + (size_t)n * CC))[i];
    __syncthreads();

    int b = tid >> 3, dg = tid & 7;
    float mur[DD];
#pragma unroll
    for (int e4 = 0; e4 < 16; e4++) {
        float4 v = ((const float4*)(mus + b * DD))[e4];
        mur[4 * e4] = v.x; mur[4 * e4 + 1] = v.y; mur[4 * e4 + 2] = v.z; mur[4 * e4 + 3] = v.w;
    }
    union { uint4 u; __nv_bfloat16 h[8]; } ph, pl;
#pragma unroll
    for (int k = 0; k < 8; k++) {
        int d = dg * 8 + k;
        float acc = 0.f;
#pragma unroll
        for (int e = 0; e < DD; e++) acc += mur[e] * W2sp[d * 65 + e];
        __nv_bfloat16 hi = __float2bfloat16(acc);
        ph.h[k] = hi;
        pl.h[k] = __float2bfloat16(acc - __bfloat162float(hi));
    }
    size_t off = (size_t)n * CC + b * DD + dg * 8;
    *(uint4*)(g_nu_hi + off) = ph.u;
    *(uint4*)(g_nu_lo + off) = pl.u;
}

// ---------------- pool = A @ nu via mma.sync bf16 (hi/lo); mu = relu(m13 + pool) ----------------
// CTA tile 64(m) x 128(c), K-chunk 32, double-buffered cp.async, 8 warps (2x4),
// 2 CTAs/SM. Last round also emits column-sum partials.
__global__ __launch_bounds__(256, 2) void k_mma(int do_colsum) {
    __shared__ __align__(16) char SB[2][20480];   // per stage: A 4KB, Bh 8KB @4096, Bl 8KB @12288

    int tid = threadIdx.x;
    int lane = tid & 31, wid = tid >> 5;
    int warpM = wid >> 2, warpN = wid & 3;   // warpM in {0,1} x 32 rows, warpN x 32 cols
    int mbase = blockIdx.y * 64;
    int cbase = blockIdx.x * 128;

    uint32_t sb0 = smem_u32(SB);
    uint32_t asb[2] = { sb0,          sb0 + 20480 };
    uint32_t bhb[2] = { sb0 + 4096,   sb0 + 24576 };
    uint32_t blb[2] = { sb0 + 12288,  sb0 + 32768 };

    float C[8][4];
#pragma unroll
    for (int i = 0; i < 8; i++)
#pragma unroll
        for (int j = 0; j < 4; j++) C[i][j] = 0.f;

    auto load_stage = [&](int ch, int buf) {
        {   // A: 64 rows x 32 k bf16 = 4KB, one cp16 per thread
            int m = tid >> 2, u = tid & 3;
            const __nv_bfloat16* g = g_Abf + (size_t)(mbase + m) * NN + ch * 32 + u * 8;
            uint32_t s = asb[buf] + m * 64 + (((u ^ ((m >> 1) & 3)) & 3) << 4);
            cp16(s, g);
        }
#pragma unroll
        for (int t = 0; t < 2; t++) {
            int i = tid + t * 256;
            int k = i >> 4, u = i & 15;
            int su = (u & 8) | ((u ^ k) & 7);
            size_t go = (size_t)(ch * 32 + k) * CC + cbase + u * 8;
            uint32_t so = k * 256 + (su << 4);
            cp16(bhb[buf] + so, g_nu_hi + go);
            cp16(blb[buf] + so, g_nu_lo + go);
        }
        asm volatile("cp.async.commit_group;\n" ::: "memory");
    };

    load_stage(0, 0);

    for (int ch = 0; ch < 32; ch++) {
        int buf = ch & 1;
        if (ch + 1 < 32) load_stage(ch + 1, buf ^ 1);
        if (ch + 1 < 32) asm volatile("cp.async.wait_group 1;\n" ::: "memory");
        else             asm volatile("cp.async.wait_group 0;\n" ::: "memory");
        __syncthreads();

#pragma unroll
        for (int ks = 0; ks < 2; ks++) {
            uint32_t a[2][4];
#pragma unroll
            for (int mt = 0; mt < 2; mt++) {
                int row = warpM * 32 + mt * 16 + (lane & 7) + ((lane >> 3) & 1) * 8;
                int unit = 2 * ks + (lane >> 4);
                uint32_t addr = asb[buf] + row * 64 + (((unit ^ ((row >> 1) & 3)) & 3) << 4);
                asm volatile("ldmatrix.sync.aligned.m8n8.x4.shared.b16 {%0,%1,%2,%3}, [%4];"
                             : "=r"(a[mt][0]), "=r"(a[mt][1]), "=r"(a[mt][2]), "=r"(a[mt][3])
                             : "r"(addr));
            }
            uint32_t bhf[4][2], blf[4][2];
#pragma unroll
            for (int pair = 0; pair < 2; pair++) {
                int k = ks * 16 + (lane & 7) + ((lane >> 3) & 1) * 8;
                int u = warpN * 4 + pair * 2 + (lane >> 4);
                int su = (u & 8) | ((u ^ k) & 7);
                uint32_t so = k * 256 + (su << 4);
                asm volatile("ldmatrix.sync.aligned.m8n8.x4.trans.shared.b16 {%0,%1,%2,%3}, [%4];"
                             : "=r"(bhf[pair * 2][0]), "=r"(bhf[pair * 2][1]),
                               "=r"(bhf[pair * 2 + 1][0]), "=r"(bhf[pair * 2 + 1][1])
                             : "r"(bhb[buf] + so));
                asm volatile("ldmatrix.sync.aligned.m8n8.x4.trans.shared.b16 {%0,%1,%2,%3}, [%4];"
                             : "=r"(blf[pair * 2][0]), "=r"(blf[pair * 2][1]),
                               "=r"(blf[pair * 2 + 1][0]), "=r"(blf[pair * 2 + 1][1])
                             : "r"(blb[buf] + so));
            }
#pragma unroll
            for (int mt = 0; mt < 2; mt++) {
#pragma unroll
                for (int nt = 0; nt < 4; nt++) {
                    float* c = C[mt * 4 + nt];
                    asm volatile(
                        "mma.sync.aligned.m16n8k16.row.col.f32.bf16.bf16.f32 "
                        "{%0,%1,%2,%3},{%4,%5,%6,%7},{%8,%9},{%0,%1,%2,%3};"
                        : "+f"(c[0]), "+f"(c[1]), "+f"(c[2]), "+f"(c[3])
                        : "r"(a[mt][0]), "r"(a[mt][1]), "r"(a[mt][2]), "r"(a[mt][3]),
                          "r"(bhf[nt][0]), "r"(bhf[nt][1]));
                    asm volatile(
                        "mma.sync.aligned.m16n8k16.row.col.f32.bf16.bf16.f32 "
                        "{%0,%1,%2,%3},{%4,%5,%6,%7},{%8,%9},{%0,%1,%2,%3};"
                        : "+f"(c[0]), "+f"(c[1]), "+f"(c[2]), "+f"(c[3])
                        : "r"(a[mt][0]), "r"(a[mt][1]), "r"(a[mt][2]), "r"(a[mt][3]),
                          "r"(blf[nt][0]), "r"(blf[nt][1]));
                }
            }
        }
        __syncthreads();
    }

    // ---- epilogue: mu = relu(m13 + pool) ----
    int g = lane >> 2, tq = lane & 3;
#pragma unroll
    for (int mt = 0; mt < 2; mt++) {
#pragma unroll
        for (int nt = 0; nt < 4; nt++) {
            const float* c = C[mt * 4 + nt];
            int row0 = mbase + warpM * 32 + mt * 16 + g;
            int col = cbase + warpN * 32 + nt * 8 + tq * 2;
            {
                const float2 m = *(const float2*)(g_m13 + (size_t)row0 * CC + col);
                float2 o;
                o.x = fmaxf(m.x + c[0], 0.f);
                o.y = fmaxf(m.y + c[1], 0.f);
                *(float2*)(g_mu + (size_t)row0 * CC + col) = o;
            }
            {
                int row1 = row0 + 8;
                const float2 m = *(const float2*)(g_m13 + (size_t)row1 * CC + col);
                float2 o;
                o.x = fmaxf(m.x + c[2], 0.f);
                o.y = fmaxf(m.y + c[3], 0.f);
                *(float2*)(g_mu + (size_t)row1 * CC + col) = o;
            }
        }
    }

    if (do_colsum) {
        float* cs = (float*)SB;
        __syncthreads();   // mu stores visible intra-CTA
        int c = tid & 127, half = tid >> 7;   // halves of 32 rows each
        const float* mp = g_mu + (size_t)(mbase + half * 32) * CC + cbase + c;
        float s = 0.f;
#pragma unroll 8
        for (int r = 0; r < 32; r++) s += mp[(size_t)r * CC];
        cs[half * 128 + c] = s;
        __syncthreads();
        if (tid < 128)
            g_part[blockIdx.y * CC + cbase + tid] = cs[tid] + cs[128 + tid];
    }
}

// ---------------- mumean + s2, one block per b ----------------
__global__ __launch_bounds__(64) void k_small(const float* __restrict__ option,
                                              const float* __restrict__ Wq1,
                                              const float* __restrict__ bq1,
                                              const float* __restrict__ Wq2,
                                              const float* __restrict__ bq2,
                                              const float* __restrict__ Wreg) {
    int b = blockIdx.x, d = threadIdx.x;
    __shared__ float msum[DD];
    float s = 0.f;
#pragma unroll
    for (int g = 0; g < 16; g++) s += g_part[g * CC + b * DD + d];
    msum[d] = s * (1.0f / (float)NN);
    __syncthreads();
    float acc = bq1[d];
#pragma unroll
    for (int e = 0; e < DD; e++) acc += msum[e] * Wq1[d * DD + e];
    g_mumean[b * DD + d] = fmaxf(acc, 0.f);
    float opt = option[b];
    float acc2 = 0.f;
#pragma unroll
    for (int j = 0; j < DD; j++)
        acc2 += (opt * Wq2[j] + bq2[j]) * Wreg[d * (2 * DD) + DD + j];
    g_s2[b * HH + d] = acc2;
}

// ---------------- final head ----------------
__global__ __launch_bounds__(256) void k_final(const float* __restrict__ Wreg,
                                               const float* __restrict__ breg,
                                               const float* __restrict__ Wq,
                                               const float* __restrict__ bq,
                                               float* __restrict__ out) {
    int b = blockIdx.y;
    int tile = blockIdx.x;
    __shared__ float Wr[HH][DD + 1];
    __shared__ float wqs[HH], s2s[HH], brs[HH];
    __shared__ float vs[8][DD];
    int tid = threadIdx.x;
    for (int i = tid; i < HH * DD; i += 256) {
        int h = i >> 6, j = i & 63;
        Wr[h][j] = Wreg[h * (2 * DD) + j];
    }
    if (tid < HH) {
        wqs[tid] = Wq[tid];
        s2s[tid] = g_s2[b * HH + tid];
        brs[tid] = breg[tid];
    }
    __syncthreads();
    int w = tid >> 5, lane = tid & 31;
    float bqv = bq[0];
    for (int s = 0; s < 8; s++) {
        int i = tile * 64 + w * 8 + s;
        if (i > NN) continue;
        const float* vptr = (i < NN) ? (g_mu + (size_t)i * CC + b * DD) : (g_mumean + b * DD);
        vs[w][lane]      = vptr[lane];
        vs[w][lane + 32] = vptr[lane + 32];
        __syncwarp();
        float r = 0.f;
#pragma unroll
        for (int hh = 0; hh < 2; hh++) {
            int h = lane + hh * 32;
            float accd = s2s[h] + brs[h];
#pragma unroll
            for (int j = 0; j < DD; j++) accd += vs[w][j] * Wr[h][j];
            r += fmaxf(accd, 0.f) * wqs[h];
        }
#pragma unroll
        for (int off = 16; off; off >>= 1) r += __shfl_down_sync(0xffffffff, r, off);
        if (lane == 0) out[b * NP1 + i] = r + bqv;
        __syncwarp();
    }
}

// ---------------- launch ----------------
extern "C" void kernel_launch(void* const* d_in, const int* in_sizes, int n_in,
                              void* d_out, int out_size) {
    const float* xv     = (const float*)d_in[0];
    const float* option = (const float*)d_in[1];
    const float* adj    = (const float*)d_in[2];
    const float* mu1w   = (const float*)d_in[3];
    const float* W2     = (const float*)d_in[4];
    const float* b2     = (const float*)d_in[5];
    const float* W3     = (const float*)d_in[6];
    const float* b3     = (const float*)d_in[7];
    const float* W4     = (const float*)d_in[8];
    const float* b4     = (const float*)d_in[9];
    const float* Wq1    = (const float*)d_in[10];
    const float* bq1    = (const float*)d_in[11];
    const float* Wq2    = (const float*)d_in[12];
    const float* bq2    = (const float*)d_in[13];
    const float* Wreg   = (const float*)d_in[14];
    const float* breg   = (const float*)d_in[15];
    const float* Wq     = (const float*)d_in[16];
    const float* bq     = (const float*)d_in[17];
    float* out = (float*)d_out;
    (void)in_sizes; (void)n_in; (void)out_size;

    k_graph<<<NN, 256>>>(adj, W4, b4, W3, b3);
    k_mu1<<<NN, 256>>>(xv, mu1w, b2, W2);
    k_mma<<<dim3(CC / 128, NN / 64), 256>>>(0);   // t=1
    k_nu<<<NN, 256>>>(W2);
    k_mma<<<dim3(CC / 128, NN / 64), 256>>>(0);   // t=2
    k_nu<<<NN, 256>>>(W2);
    k_mma<<<dim3(CC / 128, NN / 64), 256>>>(1);   // t=3 (+colsum)
    k_small<<<32, 64>>>(option, Wq1, bq1, Wq2, bq2, Wreg);
    k_final<<<dim3(17, BB), 256>>>(Wreg, breg, Wq, bq, out);
}

// round 6
// speedup vs baseline: 1.1673x; 1.1673x over previous
#include <cuda_runtime.h>
#include <cuda_bf16.h>
#include <cstdint>

#define NN 1024
#define BB 32
#define FF 32
#define DD 64
#define HH 64
#define CC 2048   // B*D
#define NP1 1025

// ---------------- scratch (static __device__, no allocs) ----------------
__device__ __nv_bfloat16 g_Abf[NN * NN];    // binarized adjacency, bf16 (exact 0/1)
__device__ float g_m13[NN * CC];            // mu_1 + mu3 + b2
__device__ float g_mu[NN * CC];             // current mu (fp32), [n][b*64+d]
__device__ __nv_bfloat16 g_nu_hi[NN * CC];  // hi part of nu = mu @ W2^T
__device__ __nv_bfloat16 g_nu_lo[NN * CC];  // lo part
__device__ float g_mu3[NN * DD];
__device__ float g_part[8 * CC];            // column-sum partials (one per 128-row mtile)
__device__ float g_mumean[BB * DD];
__device__ float g_s2[BB * HH];

// ---------------- helpers ----------------
__device__ __forceinline__ uint32_t smem_u32(const void* p) {
    uint32_t a;
    asm("{ .reg .u64 t; cvta.to.shared.u64 t, %1; cvt.u32.u64 %0, t; }" : "=r"(a) : "l"(p));
    return a;
}
__device__ __forceinline__ void cp16(uint32_t saddr, const void* gaddr) {
    asm volatile("cp.async.cg.shared.global [%0], [%1], 16;\n" :: "r"(saddr), "l"(gaddr));
}

// ---------------- adjacency: binarize to bf16 + mu3 (one adj read) ----------------
__global__ __launch_bounds__(256) void k_graph(const float* __restrict__ adj,
                                               const float* __restrict__ W4,
                                               const float* __restrict__ b4,
                                               const float* __restrict__ W3,
                                               const float* __restrict__ b3) {
    int n = blockIdx.x;
    int tid = threadIdx.x;
    __shared__ float arow[NN];
    __shared__ float part[4][DD];
    __shared__ float mu4s[DD];

    {
        float4 v = ((const float4*)(adj + (size_t)n * NN))[tid];
        arow[tid * 4 + 0] = v.x;
        arow[tid * 4 + 1] = v.y;
        arow[tid * 4 + 2] = v.z;
        arow[tid * 4 + 3] = v.w;
        union { uint2 u; __nv_bfloat16 h[4]; } pk;
        pk.h[0] = __float2bfloat16(v.x > 0.f ? 1.f : 0.f);
        pk.h[1] = __float2bfloat16(v.y > 0.f ? 1.f : 0.f);
        pk.h[2] = __float2bfloat16(v.z > 0.f ? 1.f : 0.f);
        pk.h[3] = __float2bfloat16(v.w > 0.f ? 1.f : 0.f);
        *(uint2*)(g_Abf + (size_t)n * NN + tid * 4) = pk.u;
    }
    __syncthreads();

    int d = tid & 63, q = tid >> 6;
    float w = W4[d], c0 = b4[d];
    float acc = 0.f;
    for (int m = q; m < NN; m += 4)
        acc += fmaxf(arow[m] * w + c0, 0.f);
    part[q][d] = acc;
    __syncthreads();
    if (tid < DD) mu4s[tid] = part[0][tid] + part[1][tid] + part[2][tid] + part[3][tid];
    __syncthreads();
    if (tid < DD) {
        int d2 = tid;
        float a = b3[d2];
#pragma unroll
        for (int e = 0; e < DD; e++) a += mu4s[e] * W3[d2 * DD + e];
        g_mu3[n * DD + d2] = a;
    }
}

// ---------------- mu_1 + m13 + first nu (fused, efficient tail) ----------------
__global__ __launch_bounds__(256) void k_mu1(const float* __restrict__ xv,
                                             const float* __restrict__ mu1w,
                                             const float* __restrict__ b2,
                                             const float* __restrict__ W2) {
    int n = blockIdx.x;
    __shared__ float xs[BB][FF];
    __shared__ float ws[FF][DD];
    __shared__ float m3[DD];
    __shared__ float mus[CC];
    __shared__ float4 W2q[16 * 64];   // [e4][d] float4 of W2 row d
    int tid = threadIdx.x;
    for (int i = tid; i < BB * FF; i += 256) {
        int b = i / FF, f = i % FF;
        xs[b][f] = xv[(b * NN + n) * FF + f];
    }
    for (int i = tid; i < FF * DD; i += 256) ws[i / DD][i % DD] = mu1w[i];
    for (int i = tid; i < 1024; i += 256) {
        int e4 = i >> 6, d = i & 63;
        W2q[i] = ((const float4*)(W2 + d * DD))[e4];
    }
    if (tid < DD) m3[tid] = g_mu3[n * DD + tid] + b2[tid];
    __syncthreads();
#pragma unroll
    for (int j = 0; j < 8; j++) {
        int c = tid + 256 * j;
        int b = c >> 6, d = c & 63;
        float acc = 0.f;
#pragma unroll
        for (int f = 0; f < FF; f++) acc += xs[b][f] * ws[f][d];
        float r = fmaxf(acc, 0.f);
        g_mu[n * CC + c] = r;
        g_m13[n * CC + c] = r + m3[d];
        mus[c] = r;
    }
    __syncthreads();

    // nu = mu @ W2^T: thread = (b, dg); d = k*8 + dg (interleaved, conflict-free)
    int b = tid >> 3, dg = tid & 7;
    const float4* mb = (const float4*)(mus + b * DD);
    float acc[8] = {};
#pragma unroll
    for (int e4 = 0; e4 < 16; e4++) {
        float4 m = mb[e4];
#pragma unroll
        for (int k = 0; k < 8; k++) {
            float4 w = W2q[e4 * 64 + k * 8 + dg];
            acc[k] += m.x * w.x + m.y * w.y + m.z * w.z + m.w * w.w;
        }
    }
    size_t base = (size_t)n * CC + b * DD + dg;
#pragma unroll
    for (int k = 0; k < 8; k++) {
        __nv_bfloat16 hi = __float2bfloat16(acc[k]);
        float lo = acc[k] - __bfloat162float(hi);
        g_nu_hi[base + k * 8] = hi;
        g_nu_lo[base + k * 8] = __float2bfloat16(lo);
    }
}

// ---------------- nu = mu @ W2^T, FLOP-bound, hi/lo bf16 ----------------
__global__ __launch_bounds__(256) void k_nu(const float* __restrict__ W2) {
    int n = blockIdx.x;
    __shared__ float4 W2q[16 * 64];
    __shared__ float mus[CC];
    int tid = threadIdx.x;
    for (int i = tid; i < 1024; i += 256) {
        int e4 = i >> 6, d = i & 63;
        W2q[i] = ((const float4*)(W2 + d * DD))[e4];
    }
    for (int i = tid; i < CC / 4; i += 256)
        ((float4*)mus)[i] = ((const float4*)(g_mu + (size_t)n * CC))[i];
    __syncthreads();

    int b = tid >> 3, dg = tid & 7;
    const float4* mb = (const float4*)(mus + b * DD);
    float acc[8] = {};
#pragma unroll
    for (int e4 = 0; e4 < 16; e4++) {
        float4 m = mb[e4];
#pragma unroll
        for (int k = 0; k < 8; k++) {
            float4 w = W2q[e4 * 64 + k * 8 + dg];
            acc[k] += m.x * w.x + m.y * w.y + m.z * w.z + m.w * w.w;
        }
    }
    size_t base = (size_t)n * CC + b * DD + dg;
#pragma unroll
    for (int k = 0; k < 8; k++) {
        __nv_bfloat16 hi = __float2bfloat16(acc[k]);
        float lo = acc[k] - __bfloat162float(hi);
        g_nu_hi[base + k * 8] = hi;
        g_nu_lo[base + k * 8] = __float2bfloat16(lo);
    }
}

// ---------------- pool = A @ nu via mma.sync bf16 (hi/lo); mu = relu(m13 + pool) ----------------
// CTA tile 128(m) x 128(c), K-chunk 32, double-buffered cp.async, 8 warps (2x4), 2 CTAs/SM.
__global__ __launch_bounds__(256, 2) void k_mma(int do_colsum) {
    __shared__ __align__(16) char SB[49152];

    int tid = threadIdx.x;
    int lane = tid & 31, wid = tid >> 5;
    int warpM = wid >> 2, warpN = wid & 3;
    int mbase = blockIdx.y * 128;
    int cbase = blockIdx.x * 128;

    uint32_t sb0 = smem_u32(SB);
    uint32_t asb[2] = { sb0,          sb0 + 8192 };
    uint32_t bhb[2] = { sb0 + 16384,  sb0 + 24576 };
    uint32_t blb[2] = { sb0 + 32768,  sb0 + 40960 };

    float C[16][4];
#pragma unroll
    for (int i = 0; i < 16; i++)
#pragma unroll
        for (int j = 0; j < 4; j++) C[i][j] = 0.f;

    auto load_stage = [&](int ch, int buf) {
#pragma unroll
        for (int t = 0; t < 2; t++) {
            int i = tid + t * 256;
            int m = i >> 2, u = i & 3;
            const __nv_bfloat16* g = g_Abf + (size_t)(mbase + m) * NN + ch * 32 + u * 8;
            uint32_t s = asb[buf] + m * 64 + (((u ^ ((m >> 1) & 3)) & 3) << 4);
            cp16(s, g);
        }
#pragma unroll
        for (int t = 0; t < 2; t++) {
            int i = tid + t * 256;
            int k = i >> 4, u = i & 15;
            int su = (u & 8) | ((u ^ k) & 7);
            size_t go = (size_t)(ch * 32 + k) * CC + cbase + u * 8;
            uint32_t so = k * 256 + (su << 4);
            cp16(bhb[buf] + so, g_nu_hi + go);
            cp16(blb[buf] + so, g_nu_lo + go);
        }
        asm volatile("cp.async.commit_group;\n" ::: "memory");
    };

    load_stage(0, 0);

    for (int ch = 0; ch < 32; ch++) {
        int buf = ch & 1;
        if (ch + 1 < 32) load_stage(ch + 1, buf ^ 1);
        if (ch + 1 < 32) asm volatile("cp.async.wait_group 1;\n" ::: "memory");
        else             asm volatile("cp.async.wait_group 0;\n" ::: "memory");
        __syncthreads();

#pragma unroll
        for (int ks = 0; ks < 2; ks++) {
            uint32_t a[4][4];
#pragma unroll
            for (int mt = 0; mt < 4; mt++) {
                int row = warpM * 64 + mt * 16 + (lane & 7) + ((lane >> 3) & 1) * 8;
                int unit = 2 * ks + (lane >> 4);
                uint32_t addr = asb[buf] + row * 64 + (((unit ^ ((row >> 1) & 3)) & 3) << 4);
                asm volatile("ldmatrix.sync.aligned.m8n8.x4.shared.b16 {%0,%1,%2,%3}, [%4];"
                             : "=r"(a[mt][0]), "=r"(a[mt][1]), "=r"(a[mt][2]), "=r"(a[mt][3])
                             : "r"(addr));
            }
            uint32_t bhf[4][2], blf[4][2];
#pragma unroll
            for (int pair = 0; pair < 2; pair++) {
                int k = ks * 16 + (lane & 7) + ((lane >> 3) & 1) * 8;
                int u = warpN * 4 + pair * 2 + (lane >> 4);
                int su = (u & 8) | ((u ^ k) & 7);
                uint32_t so = k * 256 + (su << 4);
                asm volatile("ldmatrix.sync.aligned.m8n8.x4.trans.shared.b16 {%0,%1,%2,%3}, [%4];"
                             : "=r"(bhf[pair * 2][0]), "=r"(bhf[pair * 2][1]),
                               "=r"(bhf[pair * 2 + 1][0]), "=r"(bhf[pair * 2 + 1][1])
                             : "r"(bhb[buf] + so));
                asm volatile("ldmatrix.sync.aligned.m8n8.x4.trans.shared.b16 {%0,%1,%2,%3}, [%4];"
                             : "=r"(blf[pair * 2][0]), "=r"(blf[pair * 2][1]),
                               "=r"(blf[pair * 2 + 1][0]), "=r"(blf[pair * 2 + 1][1])
                             : "r"(blb[buf] + so));
            }
#pragma unroll
            for (int mt = 0; mt < 4; mt++) {
#pragma unroll
                for (int nt = 0; nt < 4; nt++) {
                    float* c = C[mt * 4 + nt];
                    asm volatile(
                        "mma.sync.aligned.m16n8k16.row.col.f32.bf16.bf16.f32 "
                        "{%0,%1,%2,%3},{%4,%5,%6,%7},{%8,%9},{%0,%1,%2,%3};"
                        : "+f"(c[0]), "+f"(c[1]), "+f"(c[2]), "+f"(c[3])
                        : "r"(a[mt][0]), "r"(a[mt][1]), "r"(a[mt][2]), "r"(a[mt][3]),
                          "r"(bhf[nt][0]), "r"(bhf[nt][1]));
                    asm volatile(
                        "mma.sync.aligned.m16n8k16.row.col.f32.bf16.bf16.f32 "
                        "{%0,%1,%2,%3},{%4,%5,%6,%7},{%8,%9},{%0,%1,%2,%3};"
                        : "+f"(c[0]), "+f"(c[1]), "+f"(c[2]), "+f"(c[3])
                        : "r"(a[mt][0]), "r"(a[mt][1]), "r"(a[mt][2]), "r"(a[mt][3]),
                          "r"(blf[nt][0]), "r"(blf[nt][1]));
                }
            }
        }
        __syncthreads();
    }

    // ---- epilogue: mu = relu(m13 + pool) ----
    int g = lane >> 2, tq = lane & 3;
#pragma unroll
    for (int mt = 0; mt < 4; mt++) {
#pragma unroll
        for (int nt = 0; nt < 4; nt++) {
            const float* c = C[mt * 4 + nt];
            int row0 = mbase + warpM * 64 + mt * 16 + g;
            int col = cbase + warpN * 32 + nt * 8 + tq * 2;
            {
                const float2 m = *(const float2*)(g_m13 + (size_t)row0 * CC + col);
                float2 o;
                o.x = fmaxf(m.x + c[0], 0.f);
                o.y = fmaxf(m.y + c[1], 0.f);
                *(float2*)(g_mu + (size_t)row0 * CC + col) = o;
            }
            {
                int row1 = row0 + 8;
                const float2 m = *(const float2*)(g_m13 + (size_t)row1 * CC + col);
                float2 o;
                o.x = fmaxf(m.x + c[2], 0.f);
                o.y = fmaxf(m.y + c[3], 0.f);
                *(float2*)(g_mu + (size_t)row1 * CC + col) = o;
            }
        }
    }

    if (do_colsum) {
        float* cs = (float*)SB;
        __syncthreads();   // mu stores visible intra-CTA; also done with SB
        int c = tid & 127, half = tid >> 7;   // halves of 64 rows each
        const float* mp = g_mu + (size_t)(mbase + half * 64) * CC + cbase + c;
        float s = 0.f;
#pragma unroll 8
        for (int r = 0; r < 64; r++) s += mp[(size_t)r * CC];
        cs[half * 128 + c] = s;
        __syncthreads();
        if (tid < 128)
            g_part[blockIdx.y * CC + cbase + tid] = cs[tid] + cs[128 + tid];
    }
}

// ---------------- mumean + s2, one block per b ----------------
__global__ __launch_bounds__(64) void k_small(const float* __restrict__ option,
                                              const float* __restrict__ Wq1,
                                              const float* __restrict__ bq1,
                                              const float* __restrict__ Wq2,
                                              const float* __restrict__ bq2,
                                              const float* __restrict__ Wreg) {
    int b = blockIdx.x, d = threadIdx.x;
    __shared__ float msum[DD];
    float s = 0.f;
#pragma unroll
    for (int g = 0; g < 8; g++) s += g_part[g * CC + b * DD + d];
    msum[d] = s * (1.0f / (float)NN);
    __syncthreads();
    float acc = bq1[d];
#pragma unroll
    for (int e = 0; e < DD; e++) acc += msum[e] * Wq1[d * DD + e];
    g_mumean[b * DD + d] = fmaxf(acc, 0.f);
    float opt = option[b];
    float acc2 = 0.f;
#pragma unroll
    for (int j = 0; j < DD; j++)
        acc2 += (opt * Wq2[j] + bq2[j]) * Wreg[d * (2 * DD) + DD + j];
    g_s2[b * HH + d] = acc2;
}

// ---------------- final head ----------------
__global__ __launch_bounds__(256) void k_final(const float* __restrict__ Wreg,
                                               const float* __restrict__ breg,
                                               const float* __restrict__ Wq,
                                               const float* __restrict__ bq,
                                               float* __restrict__ out) {
    int b = blockIdx.y;
    int tile = blockIdx.x;
    __shared__ float Wr[HH][DD + 1];
    __shared__ float wqs[HH], s2s[HH], brs[HH];
    __shared__ float vs[8][DD];
    int tid = threadIdx.x;
    for (int i = tid; i < HH * DD; i += 256) {
        int h = i >> 6, j = i & 63;
        Wr[h][j] = Wreg[h * (2 * DD) + j];
    }
    if (tid < HH) {
        wqs[tid] = Wq[tid];
        s2s[tid] = g_s2[b * HH + tid];
        brs[tid] = breg[tid];
    }
    __syncthreads();
    int w = tid >> 5, lane = tid & 31;
    float bqv = bq[0];
    for (int s = 0; s < 8; s++) {
        int i = tile * 64 + w * 8 + s;
        if (i > NN) continue;
        const float* vptr = (i < NN) ? (g_mu + (size_t)i * CC + b * DD) : (g_mumean + b * DD);
        vs[w][lane]      = vptr[lane];
        vs[w][lane + 32] = vptr[lane + 32];
        __syncwarp();
        float r = 0.f;
#pragma unroll
        for (int hh = 0; hh < 2; hh++) {
            int h = lane + hh * 32;
            float accd = s2s[h] + brs[h];
#pragma unroll
            for (int j = 0; j < DD; j++) accd += vs[w][j] * Wr[h][j];
            r += fmaxf(accd, 0.f) * wqs[h];
        }
#pragma unroll
        for (int off = 16; off; off >>= 1) r += __shfl_down_sync(0xffffffff, r, off);
        if (lane == 0) out[b * NP1 + i] = r + bqv;
        __syncwarp();
    }
}

// ---------------- launch ----------------
extern "C" void kernel_launch(void* const* d_in, const int* in_sizes, int n_in,
                              void* d_out, int out_size) {
    const float* xv     = (const float*)d_in[0];
    const float* option = (const float*)d_in[1];
    const float* adj    = (const float*)d_in[2];
    const float* mu1w   = (const float*)d_in[3];
    const float* W2     = (const float*)d_in[4];
    const float* b2     = (const float*)d_in[5];
    const float* W3     = (const float*)d_in[6];
    const float* b3     = (const float*)d_in[7];
    const float* W4     = (const float*)d_in[8];
    const float* b4     = (const float*)d_in[9];
    const float* Wq1    = (const float*)d_in[10];
    const float* bq1    = (const float*)d_in[11];
    const float* Wq2    = (const float*)d_in[12];
    const float* bq2    = (const float*)d_in[13];
    const float* Wreg   = (const float*)d_in[14];
    const float* breg   = (const float*)d_in[15];
    const float* Wq     = (const float*)d_in[16];
    const float* bq     = (const float*)d_in[17];
    float* out = (float*)d_out;
    (void)in_sizes; (void)n_in; (void)out_size;

    k_graph<<<NN, 256>>>(adj, W4, b4, W3, b3);
    k_mu1<<<NN, 256>>>(xv, mu1w, b2, W2);
    k_mma<<<dim3(CC / 128, NN / 128), 256>>>(0);   // t=1
    k_nu<<<NN, 256>>>(W2);
    k_mma<<<dim3(CC / 128, NN / 128), 256>>>(0);   // t=2
    k_nu<<<NN, 256>>>(W2);
    k_mma<<<dim3(CC / 128, NN / 128), 256>>>(1);   // t=3 (+colsum)
    k_small<<<32, 64>>>(option, Wq1, bq1, Wq2, bq2, Wreg);
    k_final<<<dim3(17, BB), 256>>>(Wreg, breg, Wq, bq, out);
}

// round 7
// speedup vs baseline: 1.2946x; 1.1091x over previous
#include <cuda_runtime.h>
#include <cuda_bf16.h>
#include <cstdint>

#define NN 1024
#define BB 32
#define FF 32
#define DD 64
#define HH 64
#define CC 2048   // B*D
#define NP1 1025

// ---------------- scratch (static __device__, no allocs) ----------------
__device__ __nv_bfloat16 g_Abf[NN * NN];    // binarized adjacency, bf16 (exact 0/1)
__device__ float g_m13[NN * CC];            // mu_1 + mu3 + b2
__device__ float g_mu[NN * CC];             // current mu (fp32), [n][b*64+d]
__device__ __nv_bfloat16 g_nu_hi[NN * CC];  // hi part of nu = mu @ W2^T
__device__ __nv_bfloat16 g_nu_lo[NN * CC];  // lo part
__device__ float g_mu3[NN * DD];
__device__ float g_part[8 * CC];            // column-sum partials (one per 128-row mtile)
__device__ float g_mumean[BB * DD];
__device__ float g_s2[BB * HH];

// ---------------- helpers ----------------
__device__ __forceinline__ uint32_t smem_u32(const void* p) {
    uint32_t a;
    asm("{ .reg .u64 t; cvta.to.shared.u64 t, %1; cvt.u32.u64 %0, t; }" : "=r"(a) : "l"(p));
    return a;
}
__device__ __forceinline__ void cp16(uint32_t saddr, const void* gaddr) {
    asm volatile("cp.async.cg.shared.global [%0], [%1], 16;\n" :: "r"(saddr), "l"(gaddr));
}

// ---------------- adjacency: binarize to bf16 + mu3 (one adj read) ----------------
__global__ __launch_bounds__(256) void k_graph(const float* __restrict__ adj,
                                               const float* __restrict__ W4,
                                               const float* __restrict__ b4,
                                               const float* __restrict__ W3,
                                               const float* __restrict__ b3) {
    int n = blockIdx.x;
    int tid = threadIdx.x;
    __shared__ float arow[NN];
    __shared__ float part[4][DD];
    __shared__ float mu4s[DD];

    {
        float4 v = ((const float4*)(adj + (size_t)n * NN))[tid];
        arow[tid * 4 + 0] = v.x;
        arow[tid * 4 + 1] = v.y;
        arow[tid * 4 + 2] = v.z;
        arow[tid * 4 + 3] = v.w;
        union { uint2 u; __nv_bfloat16 h[4]; } pk;
        pk.h[0] = __float2bfloat16(v.x > 0.f ? 1.f : 0.f);
        pk.h[1] = __float2bfloat16(v.y > 0.f ? 1.f : 0.f);
        pk.h[2] = __float2bfloat16(v.z > 0.f ? 1.f : 0.f);
        pk.h[3] = __float2bfloat16(v.w > 0.f ? 1.f : 0.f);
        *(uint2*)(g_Abf + (size_t)n * NN + tid * 4) = pk.u;
    }
    __syncthreads();

    int d = tid & 63, q = tid >> 6;
    float w = W4[d], c0 = b4[d];
    float acc = 0.f;
    for (int m = q; m < NN; m += 4)
        acc += fmaxf(arow[m] * w + c0, 0.f);
    part[q][d] = acc;
    __syncthreads();
    if (tid < DD) mu4s[tid] = part[0][tid] + part[1][tid] + part[2][tid] + part[3][tid];
    __syncthreads();
    if (tid < DD) {
        int d2 = tid;
        float a = b3[d2];
#pragma unroll
        for (int e = 0; e < DD; e++) a += mu4s[e] * W3[d2 * DD + e];
        g_mu3[n * DD + d2] = a;
    }
}

// ---------------- mu_1 + m13 + first nu (fused, efficient tail) ----------------
__global__ __launch_bounds__(256) void k_mu1(const float* __restrict__ xv,
                                             const float* __restrict__ mu1w,
                                             const float* __restrict__ b2,
                                             const float* __restrict__ W2) {
    int n = blockIdx.x;
    __shared__ float xs[BB][FF];
    __shared__ float ws[FF][DD];
    __shared__ float m3[DD];
    __shared__ float mus[CC];
    __shared__ float4 W2q[16 * 64];   // [e4][d] float4 of W2 row d
    int tid = threadIdx.x;
    for (int i = tid; i < BB * FF; i += 256) {
        int b = i / FF, f = i % FF;
        xs[b][f] = xv[(b * NN + n) * FF + f];
    }
    for (int i = tid; i < FF * DD; i += 256) ws[i / DD][i % DD] = mu1w[i];
    for (int i = tid; i < 1024; i += 256) {
        int d = i >> 4, e4 = i & 15;   // coalesced global read
        W2q[e4 * 64 + d] = ((const float4*)(W2 + d * DD))[e4];
    }
    if (tid < DD) m3[tid] = g_mu3[n * DD + tid] + b2[tid];
    __syncthreads();
#pragma unroll
    for (int j = 0; j < 8; j++) {
        int c = tid + 256 * j;
        int b = c >> 6, d = c & 63;
        float acc = 0.f;
#pragma unroll
        for (int f = 0; f < FF; f++) acc += xs[b][f] * ws[f][d];
        float r = fmaxf(acc, 0.f);
        g_mu[n * CC + c] = r;
        g_m13[n * CC + c] = r + m3[d];
        mus[c] = r;
    }
    __syncthreads();

    // nu = mu @ W2^T: thread = (b, dg); d = k*8 + dg (interleaved, conflict-free)
    int b = tid >> 3, dg = tid & 7;
    const float4* mb = (const float4*)(mus + b * DD);
    float acc[8] = {};
#pragma unroll
    for (int e4 = 0; e4 < 16; e4++) {
        float4 m = mb[e4];
#pragma unroll
        for (int k = 0; k < 8; k++) {
            float4 w = W2q[e4 * 64 + k * 8 + dg];
            acc[k] += m.x * w.x + m.y * w.y + m.z * w.z + m.w * w.w;
        }
    }
    size_t base = (size_t)n * CC + b * DD + dg;
#pragma unroll
    for (int k = 0; k < 8; k++) {
        __nv_bfloat16 hi = __float2bfloat16(acc[k]);
        float lo = acc[k] - __bfloat162float(hi);
        g_nu_hi[base + k * 8] = hi;
        g_nu_lo[base + k * 8] = __float2bfloat16(lo);
    }
}

// ---------------- nu = mu @ W2^T, 4 rows per block (W2 smem reuse x4) ----------------
__global__ __launch_bounds__(256) void k_nu(const float* __restrict__ W2) {
    int n0 = blockIdx.x * 4;
    __shared__ float4 W2q[16 * 64];   // 16 KB
    __shared__ float mus[4][CC];      // 32 KB
    int tid = threadIdx.x;
    for (int i = tid; i < 1024; i += 256) {
        int d = i >> 4, e4 = i & 15;   // coalesced global read
        W2q[e4 * 64 + d] = ((const float4*)(W2 + d * DD))[e4];
    }
    // 4 rows x 512 float4 = 2048 loads / 256 threads = 8 each, coalesced
    for (int i = tid; i < 4 * (CC / 4); i += 256) {
        int r = i >> 9, j = i & 511;
        ((float4*)mus[r])[j] = ((const float4*)(g_mu + (size_t)(n0 + r) * CC))[j];
    }
    __syncthreads();

    int b = tid >> 3, dg = tid & 7;
    float acc[4][8] = {};
#pragma unroll
    for (int e4 = 0; e4 < 16; e4++) {
        float4 m0 = ((const float4*)(mus[0] + b * DD))[e4];
        float4 m1 = ((const float4*)(mus[1] + b * DD))[e4];
        float4 m2 = ((const float4*)(mus[2] + b * DD))[e4];
        float4 m3v = ((const float4*)(mus[3] + b * DD))[e4];
#pragma unroll
        for (int k = 0; k < 8; k++) {
            float4 w = W2q[e4 * 64 + k * 8 + dg];
            acc[0][k] += m0.x * w.x + m0.y * w.y + m0.z * w.z + m0.w * w.w;
            acc[1][k] += m1.x * w.x + m1.y * w.y + m1.z * w.z + m1.w * w.w;
            acc[2][k] += m2.x * w.x + m2.y * w.y + m2.z * w.z + m2.w * w.w;
            acc[3][k] += m3v.x * w.x + m3v.y * w.y + m3v.z * w.z + m3v.w * w.w;
        }
    }
#pragma unroll
    for (int r = 0; r < 4; r++) {
        size_t base = (size_t)(n0 + r) * CC + b * DD + dg;
#pragma unroll
        for (int k = 0; k < 8; k++) {
            float a = acc[r][k];
            __nv_bfloat16 hi = __float2bfloat16(a);
            float lo = a - __bfloat162float(hi);
            g_nu_hi[base + k * 8] = hi;
            g_nu_lo[base + k * 8] = __float2bfloat16(lo);
        }
    }
}

// ---------------- pool = A @ nu via mma.sync bf16 (hi/lo); mu = relu(m13 + pool) ----------------
// CTA tile 128(m) x 128(c), K-chunk 32, double-buffered cp.async, 8 warps (2x4), 2 CTAs/SM.
__global__ __launch_bounds__(256, 2) void k_mma(int do_colsum) {
    __shared__ __align__(16) char SB[49152];

    int tid = threadIdx.x;
    int lane = tid & 31, wid = tid >> 5;
    int warpM = wid >> 2, warpN = wid & 3;
    int mbase = blockIdx.y * 128;
    int cbase = blockIdx.x * 128;

    uint32_t sb0 = smem_u32(SB);
    uint32_t asb[2] = { sb0,          sb0 + 8192 };
    uint32_t bhb[2] = { sb0 + 16384,  sb0 + 24576 };
    uint32_t blb[2] = { sb0 + 32768,  sb0 + 40960 };

    float C[16][4];
#pragma unroll
    for (int i = 0; i < 16; i++)
#pragma unroll
        for (int j = 0; j < 4; j++) C[i][j] = 0.f;

    auto load_stage = [&](int ch, int buf) {
#pragma unroll
        for (int t = 0; t < 2; t++) {
            int i = tid + t * 256;
            int m = i >> 2, u = i & 3;
            const __nv_bfloat16* g = g_Abf + (size_t)(mbase + m) * NN + ch * 32 + u * 8;
            uint32_t s = asb[buf] + m * 64 + (((u ^ ((m >> 1) & 3)) & 3) << 4);
            cp16(s, g);
        }
#pragma unroll
        for (int t = 0; t < 2; t++) {
            int i = tid + t * 256;
            int k = i >> 4, u = i & 15;
            int su = (u & 8) | ((u ^ k) & 7);
            size_t go = (size_t)(ch * 32 + k) * CC + cbase + u * 8;
            uint32_t so = k * 256 + (su << 4);
            cp16(bhb[buf] + so, g_nu_hi + go);
            cp16(blb[buf] + so, g_nu_lo + go);
        }
        asm volatile("cp.async.commit_group;\n" ::: "memory");
    };

    load_stage(0, 0);

    for (int ch = 0; ch < 32; ch++) {
        int buf = ch & 1;
        if (ch + 1 < 32) load_stage(ch + 1, buf ^ 1);
        if (ch + 1 < 32) asm volatile("cp.async.wait_group 1;\n" ::: "memory");
        else             asm volatile("cp.async.wait_group 0;\n" ::: "memory");
        __syncthreads();

#pragma unroll
        for (int ks = 0; ks < 2; ks++) {
            uint32_t a[4][4];
#pragma unroll
            for (int mt = 0; mt < 4; mt++) {
                int row = warpM * 64 + mt * 16 + (lane & 7) + ((lane >> 3) & 1) * 8;
                int unit = 2 * ks + (lane >> 4);
                uint32_t addr = asb[buf] + row * 64 + (((unit ^ ((row >> 1) & 3)) & 3) << 4);
                asm volatile("ldmatrix.sync.aligned.m8n8.x4.shared.b16 {%0,%1,%2,%3}, [%4];"
                             : "=r"(a[mt][0]), "=r"(a[mt][1]), "=r"(a[mt][2]), "=r"(a[mt][3])
                             : "r"(addr));
            }
            uint32_t bhf[4][2], blf[4][2];
#pragma unroll
            for (int pair = 0; pair < 2; pair++) {
                int k = ks * 16 + (lane & 7) + ((lane >> 3) & 1) * 8;
                int u = warpN * 4 + pair * 2 + (lane >> 4);
                int su = (u & 8) | ((u ^ k) & 7);
                uint32_t so = k * 256 + (su << 4);
                asm volatile("ldmatrix.sync.aligned.m8n8.x4.trans.shared.b16 {%0,%1,%2,%3}, [%4];"
                             : "=r"(bhf[pair * 2][0]), "=r"(bhf[pair * 2][1]),
                               "=r"(bhf[pair * 2 + 1][0]), "=r"(bhf[pair * 2 + 1][1])
                             : "r"(bhb[buf] + so));
                asm volatile("ldmatrix.sync.aligned.m8n8.x4.trans.shared.b16 {%0,%1,%2,%3}, [%4];"
                             : "=r"(blf[pair * 2][0]), "=r"(blf[pair * 2][1]),
                               "=r"(blf[pair * 2 + 1][0]), "=r"(blf[pair * 2 + 1][1])
                             : "r"(blb[buf] + so));
            }
#pragma unroll
            for (int mt = 0; mt < 4; mt++) {
#pragma unroll
                for (int nt = 0; nt < 4; nt++) {
                    float* c = C[mt * 4 + nt];
                    asm volatile(
                        "mma.sync.aligned.m16n8k16.row.col.f32.bf16.bf16.f32 "
                        "{%0,%1,%2,%3},{%4,%5,%6,%7},{%8,%9},{%0,%1,%2,%3};"
                        : "+f"(c[0]), "+f"(c[1]), "+f"(c[2]), "+f"(c[3])
                        : "r"(a[mt][0]), "r"(a[mt][1]), "r"(a[mt][2]), "r"(a[mt][3]),
                          "r"(bhf[nt][0]), "r"(bhf[nt][1]));
                    asm volatile(
                        "mma.sync.aligned.m16n8k16.row.col.f32.bf16.bf16.f32 "
                        "{%0,%1,%2,%3},{%4,%5,%6,%7},{%8,%9},{%0,%1,%2,%3};"
                        : "+f"(c[0]), "+f"(c[1]), "+f"(c[2]), "+f"(c[3])
                        : "r"(a[mt][0]), "r"(a[mt][1]), "r"(a[mt][2]), "r"(a[mt][3]),
                          "r"(blf[nt][0]), "r"(blf[nt][1]));
                }
            }
        }
        __syncthreads();
    }

    // ---- epilogue: mu = relu(m13 + pool) ----
    int g = lane >> 2, tq = lane & 3;
#pragma unroll
    for (int mt = 0; mt < 4; mt++) {
#pragma unroll
        for (int nt = 0; nt < 4; nt++) {
            const float* c = C[mt * 4 + nt];
            int row0 = mbase + warpM * 64 + mt * 16 + g;
            int col = cbase + warpN * 32 + nt * 8 + tq * 2;
            {
                const float2 m = *(const float2*)(g_m13 + (size_t)row0 * CC + col);
                float2 o;
                o.x = fmaxf(m.x + c[0], 0.f);
                o.y = fmaxf(m.y + c[1], 0.f);
                *(float2*)(g_mu + (size_t)row0 * CC + col) = o;
            }
            {
                int row1 = row0 + 8;
                const float2 m = *(const float2*)(g_m13 + (size_t)row1 * CC + col);
                float2 o;
                o.x = fmaxf(m.x + c[2], 0.f);
                o.y = fmaxf(m.y + c[3], 0.f);
                *(float2*)(g_mu + (size_t)row1 * CC + col) = o;
            }
        }
    }

    if (do_colsum) {
        float* cs = (float*)SB;
        __syncthreads();   // mu stores visible intra-CTA; also done with SB
        int c = tid & 127, half = tid >> 7;   // halves of 64 rows each
        const float* mp = g_mu + (size_t)(mbase + half * 64) * CC + cbase + c;
        float s = 0.f;
#pragma unroll 8
        for (int r = 0; r < 64; r++) s += mp[(size_t)r * CC];
        cs[half * 128 + c] = s;
        __syncthreads();
        if (tid < 128)
            g_part[blockIdx.y * CC + cbase + tid] = cs[tid] + cs[128 + tid];
    }
}

// ---------------- mumean + s2, one block per b ----------------
__global__ __launch_bounds__(64) void k_small(const float* __restrict__ option,
                                              const float* __restrict__ Wq1,
                                              const float* __restrict__ bq1,
                                              const float* __restrict__ Wq2,
                                              const float* __restrict__ bq2,
                                              const float* __restrict__ Wreg) {
    int b = blockIdx.x, d = threadIdx.x;
    __shared__ float msum[DD];
    float s = 0.f;
#pragma unroll
    for (int g = 0; g < 8; g++) s += g_part[g * CC + b * DD + d];
    msum[d] = s * (1.0f / (float)NN);
    __syncthreads();
    float acc = bq1[d];
#pragma unroll
    for (int e = 0; e < DD; e++) acc += msum[e] * Wq1[d * DD + e];
    g_mumean[b * DD + d] = fmaxf(acc, 0.f);
    float opt = option[b];
    float acc2 = 0.f;
#pragma unroll
    for (int j = 0; j < DD; j++)
        acc2 += (opt * Wq2[j] + bq2[j]) * Wreg[d * (2 * DD) + DD + j];
    g_s2[b * HH + d] = acc2;
}

// ---------------- final head ----------------
__global__ __launch_bounds__(256) void k_final(const float* __restrict__ Wreg,
                                               const float* __restrict__ breg,
                                               const float* __restrict__ Wq,
                                               const float* __restrict__ bq,
                                               float* __restrict__ out) {
    int b = blockIdx.y;
    int tile = blockIdx.x;
    __shared__ float Wr[HH][DD + 1];
    __shared__ float wqs[HH], s2s[HH], brs[HH];
    __shared__ float vs[8][DD];
    int tid = threadIdx.x;
    for (int i = tid; i < HH * DD; i += 256) {
        int h = i >> 6, j = i & 63;
        Wr[h][j] = Wreg[h * (2 * DD) + j];
    }
    if (tid < HH) {
        wqs[tid] = Wq[tid];
        s2s[tid] = g_s2[b * HH + tid];
        brs[tid] = breg[tid];
    }
    __syncthreads();
    int w = tid >> 5, lane = tid & 31;
    float bqv = bq[0];
    for (int s = 0; s < 8; s++) {
        int i = tile * 64 + w * 8 + s;
        if (i > NN) continue;
        const float* vptr = (i < NN) ? (g_mu + (size_t)i * CC + b * DD) : (g_mumean + b * DD);
        vs[w][lane]      = vptr[lane];
        vs[w][lane + 32] = vptr[lane + 32];
        __syncwarp();
        float r = 0.f;
#pragma unroll
        for (int hh = 0; hh < 2; hh++) {
            int h = lane + hh * 32;
            float accd = s2s[h] + brs[h];
#pragma unroll
            for (int j = 0; j < DD; j++) accd += vs[w][j] * Wr[h][j];
            r += fmaxf(accd, 0.f) * wqs[h];
        }
#pragma unroll
        for (int off = 16; off; off >>= 1) r += __shfl_down_sync(0xffffffff, r, off);
        if (lane == 0) out[b * NP1 + i] = r + bqv;
        __syncwarp();
    }
}

// ---------------- launch ----------------
extern "C" void kernel_launch(void* const* d_in, const int* in_sizes, int n_in,
                              void* d_out, int out_size) {
    const float* xv     = (const float*)d_in[0];
    const float* option = (const float*)d_in[1];
    const float* adj    = (const float*)d_in[2];
    const float* mu1w   = (const float*)d_in[3];
    const float* W2     = (const float*)d_in[4];
    const float* b2     = (const float*)d_in[5];
    const float* W3     = (const float*)d_in[6];
    const float* b3     = (const float*)d_in[7];
    const float* W4     = (const float*)d_in[8];
    const float* b4     = (const float*)d_in[9];
    const float* Wq1    = (const float*)d_in[10];
    const float* bq1    = (const float*)d_in[11];
    const float* Wq2    = (const float*)d_in[12];
    const float* bq2    = (const float*)d_in[13];
    const float* Wreg   = (const float*)d_in[14];
    const float* breg   = (const float*)d_in[15];
    const float* Wq     = (const float*)d_in[16];
    const float* bq     = (const float*)d_in[17];
    float* out = (float*)d_out;
    (void)in_sizes; (void)n_in; (void)out_size;

    k_graph<<<NN, 256>>>(adj, W4, b4, W3, b3);
    k_mu1<<<NN, 256>>>(xv, mu1w, b2, W2);
    k_mma<<<dim3(CC / 128, NN / 128), 256>>>(0);   // t=1
    k_nu<<<NN / 4, 256>>>(W2);
    k_mma<<<dim3(CC / 128, NN / 128), 256>>>(0);   // t=2
    k_nu<<<NN / 4, 256>>>(W2);
    k_mma<<<dim3(CC / 128, NN / 128), 256>>>(1);   // t=3 (+colsum)
    k_small<<<32, 64>>>(option, Wq1, bq1, Wq2, bq2, Wreg);
    k_final<<<dim3(17, BB), 256>>>(Wreg, breg, Wq, bq, out);
}

// round 8
// speedup vs baseline: 1.3855x; 1.0702x over previous
#include <cuda_runtime.h>
#include <cuda_bf16.h>
#include <cstdint>

#define NN 1024
#define BB 32
#define FF 32
#define DD 64
#define HH 64
#define CC 2048   // B*D
#define NP1 1025

// ---------------- scratch (static __device__, no allocs) ----------------
__device__ __nv_bfloat16 g_Abf[NN * NN];    // binarized adjacency, bf16 (exact 0/1)
__device__ float g_m13[NN * CC];            // mu_1 + mu3 + b2
__device__ float g_mu[NN * CC];             // current mu (fp32), [n][b*64+d]
__device__ __nv_bfloat16 g_nu_hi[NN * CC];  // hi part of nu = mu @ W2^T
__device__ __nv_bfloat16 g_nu_lo[NN * CC];  // lo part
__device__ float g_mu3[NN * DD];
__device__ float g_part[8 * CC];            // column-sum partials (one per 128-row mtile)
__device__ float g_mumean[BB * DD];
__device__ float g_s2[BB * HH];

// ---------------- helpers ----------------
__device__ __forceinline__ uint32_t smem_u32(const void* p) {
    uint32_t a;
    asm("{ .reg .u64 t; cvta.to.shared.u64 t, %1; cvt.u32.u64 %0, t; }" : "=r"(a) : "l"(p));
    return a;
}
__device__ __forceinline__ void cp16(uint32_t saddr, const void* gaddr) {
    asm volatile("cp.async.cg.shared.global [%0], [%1], 16;\n" :: "r"(saddr), "l"(gaddr));
}

// ---------------- adjacency: binarize to bf16 + mu3 (one adj read) ----------------
__global__ __launch_bounds__(256) void k_graph(const float* __restrict__ adj,
                                               const float* __restrict__ W4,
                                               const float* __restrict__ b4,
                                               const float* __restrict__ W3,
                                               const float* __restrict__ b3) {
    int n = blockIdx.x;
    int tid = threadIdx.x;
    __shared__ float arow[NN];
    __shared__ float part[4][DD];
    __shared__ float mu4s[DD];

    {
        float4 v = ((const float4*)(adj + (size_t)n * NN))[tid];
        arow[tid * 4 + 0] = v.x;
        arow[tid * 4 + 1] = v.y;
        arow[tid * 4 + 2] = v.z;
        arow[tid * 4 + 3] = v.w;
        union { uint2 u; __nv_bfloat16 h[4]; } pk;
        pk.h[0] = __float2bfloat16(v.x > 0.f ? 1.f : 0.f);
        pk.h[1] = __float2bfloat16(v.y > 0.f ? 1.f : 0.f);
        pk.h[2] = __float2bfloat16(v.z > 0.f ? 1.f : 0.f);
        pk.h[3] = __float2bfloat16(v.w > 0.f ? 1.f : 0.f);
        *(uint2*)(g_Abf + (size_t)n * NN + tid * 4) = pk.u;
    }
    __syncthreads();

    int d = tid & 63, q = tid >> 6;
    float w = W4[d], c0 = b4[d];
    float acc = 0.f;
    for (int m = q; m < NN; m += 4)
        acc += fmaxf(arow[m] * w + c0, 0.f);
    part[q][d] = acc;
    __syncthreads();
    if (tid < DD) mu4s[tid] = part[0][tid] + part[1][tid] + part[2][tid] + part[3][tid];
    __syncthreads();
    if (tid < DD) {
        int d2 = tid;
        float a = b3[d2];
#pragma unroll
        for (int e = 0; e < DD; e++) a += mu4s[e] * W3[d2 * DD + e];
        g_mu3[n * DD + d2] = a;
    }
}

// ---------------- mu_1 + m13 + first nu (fused, efficient tail) ----------------
__global__ __launch_bounds__(256) void k_mu1(const float* __restrict__ xv,
                                             const float* __restrict__ mu1w,
                                             const float* __restrict__ b2,
                                             const float* __restrict__ W2) {
    int n = blockIdx.x;
    __shared__ float xs[BB][FF];
    __shared__ float ws[FF][DD];
    __shared__ float m3[DD];
    __shared__ float mus[CC];
    __shared__ float4 W2q[16 * 64];   // [e4][d] float4 of W2 row d
    int tid = threadIdx.x;
    for (int i = tid; i < BB * FF; i += 256) {
        int b = i / FF, f = i % FF;
        xs[b][f] = xv[(b * NN + n) * FF + f];
    }
    for (int i = tid; i < FF * DD; i += 256) ws[i / DD][i % DD] = mu1w[i];
    for (int i = tid; i < 1024; i += 256) {
        int d = i >> 4, e4 = i & 15;   // coalesced global read
        W2q[e4 * 64 + d] = ((const float4*)(W2 + d * DD))[e4];
    }
    if (tid < DD) m3[tid] = g_mu3[n * DD + tid] + b2[tid];
    __syncthreads();
#pragma unroll
    for (int j = 0; j < 8; j++) {
        int c = tid + 256 * j;
        int b = c >> 6, d = c & 63;
        float acc = 0.f;
#pragma unroll
        for (int f = 0; f < FF; f++) acc += xs[b][f] * ws[f][d];
        float r = fmaxf(acc, 0.f);
        g_mu[n * CC + c] = r;
        g_m13[n * CC + c] = r + m3[d];
        mus[c] = r;
    }
    __syncthreads();

    // nu = mu @ W2^T: thread = (b, dg); d = k*8 + dg (interleaved, conflict-free)
    int b = tid >> 3, dg = tid & 7;
    const float4* mb = (const float4*)(mus + b * DD);
    float acc[8] = {};
#pragma unroll
    for (int e4 = 0; e4 < 16; e4++) {
        float4 m = mb[e4];
#pragma unroll
        for (int k = 0; k < 8; k++) {
            float4 w = W2q[e4 * 64 + k * 8 + dg];
            acc[k] += m.x * w.x + m.y * w.y + m.z * w.z + m.w * w.w;
        }
    }
    size_t base = (size_t)n * CC + b * DD + dg;
#pragma unroll
    for (int k = 0; k < 8; k++) {
        __nv_bfloat16 hi = __float2bfloat16(acc[k]);
        float lo = acc[k] - __bfloat162float(hi);
        g_nu_hi[base + k * 8] = hi;
        g_nu_lo[base + k * 8] = __float2bfloat16(lo);
    }
}

// ---------------- nu = mu @ W2^T, 4 rows per block (W2 smem reuse x4) ----------------
__global__ __launch_bounds__(256) void k_nu(const float* __restrict__ W2) {
    int n0 = blockIdx.x * 4;
    __shared__ float4 W2q[16 * 64];   // 16 KB
    __shared__ float mus[4][CC];      // 32 KB
    int tid = threadIdx.x;
    for (int i = tid; i < 1024; i += 256) {
        int d = i >> 4, e4 = i & 15;   // coalesced global read
        W2q[e4 * 64 + d] = ((const float4*)(W2 + d * DD))[e4];
    }
    for (int i = tid; i < 4 * (CC / 4); i += 256) {
        int r = i >> 9, j = i & 511;
        ((float4*)mus[r])[j] = ((const float4*)(g_mu + (size_t)(n0 + r) * CC))[j];
    }
    __syncthreads();

    int b = tid >> 3, dg = tid & 7;
    float acc[4][8] = {};
#pragma unroll
    for (int e4 = 0; e4 < 16; e4++) {
        float4 m0 = ((const float4*)(mus[0] + b * DD))[e4];
        float4 m1 = ((const float4*)(mus[1] + b * DD))[e4];
        float4 m2 = ((const float4*)(mus[2] + b * DD))[e4];
        float4 m3v = ((const float4*)(mus[3] + b * DD))[e4];
#pragma unroll
        for (int k = 0; k < 8; k++) {
            float4 w = W2q[e4 * 64 + k * 8 + dg];
            acc[0][k] += m0.x * w.x + m0.y * w.y + m0.z * w.z + m0.w * w.w;
            acc[1][k] += m1.x * w.x + m1.y * w.y + m1.z * w.z + m1.w * w.w;
            acc[2][k] += m2.x * w.x + m2.y * w.y + m2.z * w.z + m2.w * w.w;
            acc[3][k] += m3v.x * w.x + m3v.y * w.y + m3v.z * w.z + m3v.w * w.w;
        }
    }
#pragma unroll
    for (int r = 0; r < 4; r++) {
        size_t base = (size_t)(n0 + r) * CC + b * DD + dg;
#pragma unroll
        for (int k = 0; k < 8; k++) {
            float a = acc[r][k];
            __nv_bfloat16 hi = __float2bfloat16(a);
            float lo = a - __bfloat162float(hi);
            g_nu_hi[base + k * 8] = hi;
            g_nu_lo[base + k * 8] = __float2bfloat16(lo);
        }
    }
}

// ---------------- pool = A @ nu via mma.sync bf16 (hi/lo); mu = relu(m13 + pool) ----------------
// CTA tile 128(m) x 64(c), K-chunk 32, double-buffered cp.async, 8 warps (4Mx2N),
// grid 256 -> genuinely 2 CTAs/SM (16 warps/SM).
__global__ __launch_bounds__(256, 2) void k_mma(int do_colsum) {
    __shared__ __align__(16) char SB[2][16384];  // per stage: A 8KB, Bh 4KB @8192, Bl 4KB @12288

    int tid = threadIdx.x;
    int lane = tid & 31, wid = tid >> 5;
    int warpM = wid >> 1, warpN = wid & 1;   // 4 x 2 warps; warp tile 32(m) x 32(c)
    int mbase = blockIdx.y * 128;
    int cbase = blockIdx.x * 64;

    uint32_t sb0 = smem_u32(SB);
    uint32_t asb[2] = { sb0,          sb0 + 16384 };
    uint32_t bhb[2] = { sb0 + 8192,   sb0 + 24576 };
    uint32_t blb[2] = { sb0 + 12288,  sb0 + 28672 };

    float C[8][4];
#pragma unroll
    for (int i = 0; i < 8; i++)
#pragma unroll
        for (int j = 0; j < 4; j++) C[i][j] = 0.f;

    auto load_stage = [&](int ch, int buf) {
        // A: 128 rows x 32 k bf16 = 8KB -> 512 units, 2 per thread
#pragma unroll
        for (int t = 0; t < 2; t++) {
            int i = tid + t * 256;
            int m = i >> 2, u = i & 3;
            const __nv_bfloat16* g = g_Abf + (size_t)(mbase + m) * NN + ch * 32 + u * 8;
            uint32_t s = asb[buf] + m * 64 + (((u ^ ((m >> 1) & 3)) & 3) << 4);
            cp16(s, g);
        }
        // B: 32 k x 64 c bf16 = 4KB each -> 256 units, 1 per thread each
        {
            int k = tid >> 3, u = tid & 7;
            int su = (u ^ k) & 7;
            size_t go = (size_t)(ch * 32 + k) * CC + cbase + u * 8;
            uint32_t so = k * 128 + (su << 4);
            cp16(bhb[buf] + so, g_nu_hi + go);
            cp16(blb[buf] + so, g_nu_lo + go);
        }
        asm volatile("cp.async.commit_group;\n" ::: "memory");
    };

    load_stage(0, 0);

    for (int ch = 0; ch < 32; ch++) {
        int buf = ch & 1;
        if (ch + 1 < 32) load_stage(ch + 1, buf ^ 1);
        if (ch + 1 < 32) asm volatile("cp.async.wait_group 1;\n" ::: "memory");
        else             asm volatile("cp.async.wait_group 0;\n" ::: "memory");
        __syncthreads();

#pragma unroll
        for (int ks = 0; ks < 2; ks++) {
            uint32_t a[2][4];
#pragma unroll
            for (int mt = 0; mt < 2; mt++) {
                int row = warpM * 32 + mt * 16 + (lane & 7) + ((lane >> 3) & 1) * 8;
                int unit = 2 * ks + (lane >> 4);
                uint32_t addr = asb[buf] + row * 64 + (((unit ^ ((row >> 1) & 3)) & 3) << 4);
                asm volatile("ldmatrix.sync.aligned.m8n8.x4.shared.b16 {%0,%1,%2,%3}, [%4];"
                             : "=r"(a[mt][0]), "=r"(a[mt][1]), "=r"(a[mt][2]), "=r"(a[mt][3])
                             : "r"(addr));
            }
            uint32_t bhf[4][2], blf[4][2];
#pragma unroll
            for (int pair = 0; pair < 2; pair++) {
                int k = ks * 16 + (lane & 7) + ((lane >> 3) & 1) * 8;
                int u = warpN * 4 + pair * 2 + (lane >> 4);
                int su = (u ^ k) & 7;
                uint32_t so = k * 128 + (su << 4);
                asm volatile("ldmatrix.sync.aligned.m8n8.x4.trans.shared.b16 {%0,%1,%2,%3}, [%4];"
                             : "=r"(bhf[pair * 2][0]), "=r"(bhf[pair * 2][1]),
                               "=r"(bhf[pair * 2 + 1][0]), "=r"(bhf[pair * 2 + 1][1])
                             : "r"(bhb[buf] + so));
                asm volatile("ldmatrix.sync.aligned.m8n8.x4.trans.shared.b16 {%0,%1,%2,%3}, [%4];"
                             : "=r"(blf[pair * 2][0]), "=r"(blf[pair * 2][1]),
                               "=r"(blf[pair * 2 + 1][0]), "=r"(blf[pair * 2 + 1][1])
                             : "r"(blb[buf] + so));
            }
#pragma unroll
            for (int mt = 0; mt < 2; mt++) {
#pragma unroll
                for (int nt = 0; nt < 4; nt++) {
                    float* c = C[mt * 4 + nt];
                    asm volatile(
                        "mma.sync.aligned.m16n8k16.row.col.f32.bf16.bf16.f32 "
                        "{%0,%1,%2,%3},{%4,%5,%6,%7},{%8,%9},{%0,%1,%2,%3};"
                        : "+f"(c[0]), "+f"(c[1]), "+f"(c[2]), "+f"(c[3])
                        : "r"(a[mt][0]), "r"(a[mt][1]), "r"(a[mt][2]), "r"(a[mt][3]),
                          "r"(bhf[nt][0]), "r"(bhf[nt][1]));
                    asm volatile(
                        "mma.sync.aligned.m16n8k16.row.col.f32.bf16.bf16.f32 "
                        "{%0,%1,%2,%3},{%4,%5,%6,%7},{%8,%9},{%0,%1,%2,%3};"
                        : "+f"(c[0]), "+f"(c[1]), "+f"(c[2]), "+f"(c[3])
                        : "r"(a[mt][0]), "r"(a[mt][1]), "r"(a[mt][2]), "r"(a[mt][3]),
                          "r"(blf[nt][0]), "r"(blf[nt][1]));
                }
            }
        }
        __syncthreads();
    }

    // ---- epilogue: mu = relu(m13 + pool) ----
    int g = lane >> 2, tq = lane & 3;
#pragma unroll
    for (int mt = 0; mt < 2; mt++) {
#pragma unroll
        for (int nt = 0; nt < 4; nt++) {
            const float* c = C[mt * 4 + nt];
            int row0 = mbase + warpM * 32 + mt * 16 + g;
            int col = cbase + warpN * 32 + nt * 8 + tq * 2;
            {
                const float2 m = *(const float2*)(g_m13 + (size_t)row0 * CC + col);
                float2 o;
                o.x = fmaxf(m.x + c[0], 0.f);
                o.y = fmaxf(m.y + c[1], 0.f);
                *(float2*)(g_mu + (size_t)row0 * CC + col) = o;
            }
            {
                int row1 = row0 + 8;
                const float2 m = *(const float2*)(g_m13 + (size_t)row1 * CC + col);
                float2 o;
                o.x = fmaxf(m.x + c[2], 0.f);
                o.y = fmaxf(m.y + c[3], 0.f);
                *(float2*)(g_mu + (size_t)row1 * CC + col) = o;
            }
        }
    }

    if (do_colsum) {
        float* cs = (float*)SB;
        __syncthreads();   // mu stores visible intra-CTA; also done with SB
        int c = tid & 63, q = tid >> 6;   // quarters of 32 rows each
        const float* mp = g_mu + (size_t)(mbase + q * 32) * CC + cbase + c;
        float s = 0.f;
#pragma unroll 8
        for (int r = 0; r < 32; r++) s += mp[(size_t)r * CC];
        cs[q * 64 + c] = s;
        __syncthreads();
        if (tid < 64)
            g_part[blockIdx.y * CC + cbase + tid] =
                cs[tid] + cs[64 + tid] + cs[128 + tid] + cs[192 + tid];
    }
}

// ---------------- mumean + s2, one block per b ----------------
__global__ __launch_bounds__(64) void k_small(const float* __restrict__ option,
                                              const float* __restrict__ Wq1,
                                              const float* __restrict__ bq1,
                                              const float* __restrict__ Wq2,
                                              const float* __restrict__ bq2,
                                              const float* __restrict__ Wreg) {
    int b = blockIdx.x, d = threadIdx.x;
    __shared__ float msum[DD];
    float s = 0.f;
#pragma unroll
    for (int g = 0; g < 8; g++) s += g_part[g * CC + b * DD + d];
    msum[d] = s * (1.0f / (float)NN);
    __syncthreads();
    float acc = bq1[d];
#pragma unroll
    for (int e = 0; e < DD; e++) acc += msum[e] * Wq1[d * DD + e];
    g_mumean[b * DD + d] = fmaxf(acc, 0.f);
    float opt = option[b];
    float acc2 = 0.f;
#pragma unroll
    for (int j = 0; j < DD; j++)
        acc2 += (opt * Wq2[j] + bq2[j]) * Wreg[d * (2 * DD) + DD + j];
    g_s2[b * HH + d] = acc2;
}

// ---------------- final head ----------------
__global__ __launch_bounds__(256) void k_final(const float* __restrict__ Wreg,
                                               const float* __restrict__ breg,
                                               const float* __restrict__ Wq,
                                               const float* __restrict__ bq,
                                               float* __restrict__ out) {
    int b = blockIdx.y;
    int tile = blockIdx.x;
    __shared__ float Wr[HH][DD + 1];
    __shared__ float wqs[HH], s2s[HH], brs[HH];
    __shared__ float vs[8][DD];
    int tid = threadIdx.x;
    for (int i = tid; i < HH * DD; i += 256) {
        int h = i >> 6, j = i & 63;
        Wr[h][j] = Wreg[h * (2 * DD) + j];
    }
    if (tid < HH) {
        wqs[tid] = Wq[tid];
        s2s[tid] = g_s2[b * HH + tid];
        brs[tid] = breg[tid];
    }
    __syncthreads();
    int w = tid >> 5, lane = tid & 31;
    float bqv = bq[0];
    for (int s = 0; s < 8; s++) {
        int i = tile * 64 + w * 8 + s;
        if (i > NN) continue;
        const float* vptr = (i < NN) ? (g_mu + (size_t)i * CC + b * DD) : (g_mumean + b * DD);
        vs[w][lane]      = vptr[lane];
        vs[w][lane + 32] = vptr[lane + 32];
        __syncwarp();
        float r = 0.f;
#pragma unroll
        for (int hh = 0; hh < 2; hh++) {
            int h = lane + hh * 32;
            float accd = s2s[h] + brs[h];
#pragma unroll
            for (int j = 0; j < DD; j++) accd += vs[w][j] * Wr[h][j];
            r += fmaxf(accd, 0.f) * wqs[h];
        }
#pragma unroll
        for (int off = 16; off; off >>= 1) r += __shfl_down_sync(0xffffffff, r, off);
        if (lane == 0) out[b * NP1 + i] = r + bqv;
        __syncwarp();
    }
}

// ---------------- launch ----------------
extern "C" void kernel_launch(void* const* d_in, const int* in_sizes, int n_in,
                              void* d_out, int out_size) {
    const float* xv     = (const float*)d_in[0];
    const float* option = (const float*)d_in[1];
    const float* adj    = (const float*)d_in[2];
    const float* mu1w   = (const float*)d_in[3];
    const float* W2     = (const float*)d_in[4];
    const float* b2     = (const float*)d_in[5];
    const float* W3     = (const float*)d_in[6];
    const float* b3     = (const float*)d_in[7];
    const float* W4     = (const float*)d_in[8];
    const float* b4     = (const float*)d_in[9];
    const float* Wq1    = (const float*)d_in[10];
    const float* bq1    = (const float*)d_in[11];
    const float* Wq2    = (const float*)d_in[12];
    const float* bq2    = (const float*)d_in[13];
    const float* Wreg   = (const float*)d_in[14];
    const float* breg   = (const float*)d_in[15];
    const float* Wq     = (const float*)d_in[16];
    const float* bq     = (const float*)d_in[17];
    float* out = (float*)d_out;
    (void)in_sizes; (void)n_in; (void)out_size;

    k_graph<<<NN, 256>>>(adj, W4, b4, W3, b3);
    k_mu1<<<NN, 256>>>(xv, mu1w, b2, W2);
    k_mma<<<dim3(CC / 64, NN / 128), 256>>>(0);   // t=1
    k_nu<<<NN / 4, 256>>>(W2);
    k_mma<<<dim3(CC / 64, NN / 128), 256>>>(0);   // t=2
    k_nu<<<NN / 4, 256>>>(W2);
    k_mma<<<dim3(CC / 64, NN / 128), 256>>>(1);   // t=3 (+colsum)
    k_small<<<32, 64>>>(option, Wq1, bq1, Wq2, bq2, Wreg);
    k_final<<<dim3(17, BB), 256>>>(Wreg, breg, Wq, bq, out);
}

// round 10
// speedup vs baseline: 1.4309x; 1.0328x over previous
#include <cuda_runtime.h>
#include <cuda_bf16.h>
#include <cstdint>

#define NN 1024
#define BB 32
#define FF 32
#define DD 64
#define HH 64
#define CC 2048   // B*D
#define NP1 1025

// ---------------- scratch (static __device__, no allocs) ----------------
__device__ __nv_bfloat16 g_Abf[NN * NN];     // binarized adjacency, bf16 (exact 0/1)
__device__ float g_m13[NN * CC];             // mu_1 + mu3 + b2
__device__ float g_mu[NN * CC];              // final-round mu (fp32)
__device__ __nv_bfloat16 g_nuA_hi[NN * CC];  // nu ping buffer
__device__ __nv_bfloat16 g_nuA_lo[NN * CC];
__device__ __nv_bfloat16 g_nuB_hi[NN * CC];  // nu pong buffer
__device__ __nv_bfloat16 g_nuB_lo[NN * CC];
__device__ float g_mu3[NN * DD];
__device__ float g_part[8 * CC];             // column-sum partials (per 128-row mtile)
__device__ float g_mumean[BB * DD];
__device__ float g_s2[BB * HH];

// ---------------- helpers ----------------
__device__ __forceinline__ uint32_t smem_u32(const void* p) {
    uint32_t a;
    asm("{ .reg .u64 t; cvta.to.shared.u64 t, %1; cvt.u32.u64 %0, t; }" : "=r"(a) : "l"(p));
    return a;
}
__device__ __forceinline__ void cp16(uint32_t saddr, const void* gaddr) {
    asm volatile("cp.async.cg.shared.global [%0], [%1], 16;\n" :: "r"(saddr), "l"(gaddr));
}

// ---------------- adjacency: binarize to bf16 + mu3 (one adj read) ----------------
__global__ __launch_bounds__(256) void k_graph(const float* __restrict__ adj,
                                               const float* __restrict__ W4,
                                               const float* __restrict__ b4,
                                               const float* __restrict__ W3,
                                               const float* __restrict__ b3) {
    int n = blockIdx.x;
    int tid = threadIdx.x;
    __shared__ float arow[NN];
    __shared__ float part[4][DD];
    __shared__ float mu4s[DD];

    {
        float4 v = ((const float4*)(adj + (size_t)n * NN))[tid];
        arow[tid * 4 + 0] = v.x;
        arow[tid * 4 + 1] = v.y;
        arow[tid * 4 + 2] = v.z;
        arow[tid * 4 + 3] = v.w;
        union { uint2 u; __nv_bfloat16 h[4]; } pk;
        pk.h[0] = __float2bfloat16(v.x > 0.f ? 1.f : 0.f);
        pk.h[1] = __float2bfloat16(v.y > 0.f ? 1.f : 0.f);
        pk.h[2] = __float2bfloat16(v.z > 0.f ? 1.f : 0.f);
        pk.h[3] = __float2bfloat16(v.w > 0.f ? 1.f : 0.f);
        *(uint2*)(g_Abf + (size_t)n * NN + tid * 4) = pk.u;
    }
    __syncthreads();

    int d = tid & 63, q = tid >> 6;
    float w = W4[d], c0 = b4[d];
    float acc = 0.f;
    for (int m = q; m < NN; m += 4)
        acc += fmaxf(arow[m] * w + c0, 0.f);
    part[q][d] = acc;
    __syncthreads();
    if (tid < DD) mu4s[tid] = part[0][tid] + part[1][tid] + part[2][tid] + part[3][tid];
    __syncthreads();
    if (tid < DD) {
        int d2 = tid;
        float a = b3[d2];
#pragma unroll
        for (int e = 0; e < DD; e++) a += mu4s[e] * W3[d2 * DD + e];
        g_mu3[n * DD + d2] = a;
    }
}

// ---------------- mu_1 + m13 + first nu (fused) -> nuA ----------------
__global__ __launch_bounds__(256) void k_mu1(const float* __restrict__ xv,
                                             const float* __restrict__ mu1w,
                                             const float* __restrict__ b2,
                                             const float* __restrict__ W2) {
    int n = blockIdx.x;
    __shared__ float xs[BB][FF];
    __shared__ float ws[FF][DD];
    __shared__ float m3[DD];
    __shared__ float mus[CC];
    __shared__ float4 W2q[16 * 64];   // [e4][d] float4 of W2 row d
    int tid = threadIdx.x;
    for (int i = tid; i < BB * FF; i += 256) {
        int b = i / FF, f = i % FF;
        xs[b][f] = xv[(b * NN + n) * FF + f];
    }
    for (int i = tid; i < FF * DD; i += 256) ws[i / DD][i % DD] = mu1w[i];
    for (int i = tid; i < 1024; i += 256) {
        int d = i >> 4, e4 = i & 15;   // coalesced global read
        W2q[e4 * 64 + d] = ((const float4*)(W2 + d * DD))[e4];
    }
    if (tid < DD) m3[tid] = g_mu3[n * DD + tid] + b2[tid];
    __syncthreads();
#pragma unroll
    for (int j = 0; j < 8; j++) {
        int c = tid + 256 * j;
        int b = c >> 6, d = c & 63;
        float acc = 0.f;
#pragma unroll
        for (int f = 0; f < FF; f++) acc += xs[b][f] * ws[f][d];
        float r = fmaxf(acc, 0.f);
        g_m13[n * CC + c] = r + m3[d];
        mus[c] = r;
    }
    __syncthreads();

    // nu = mu @ W2^T: thread = (b, dg); d = k*8 + dg (interleaved, conflict-free)
    int b = tid >> 3, dg = tid & 7;
    const float4* mb = (const float4*)(mus + b * DD);
    float acc[8] = {};
#pragma unroll
    for (int e4 = 0; e4 < 16; e4++) {
        float4 m = mb[e4];
#pragma unroll
        for (int k = 0; k < 8; k++) {
            float4 w = W2q[e4 * 64 + k * 8 + dg];
            acc[k] += m.x * w.x + m.y * w.y + m.z * w.z + m.w * w.w;
        }
    }
    size_t base = (size_t)n * CC + b * DD + dg;
#pragma unroll
    for (int k = 0; k < 8; k++) {
        __nv_bfloat16 hi = __float2bfloat16(acc[k]);
        float lo = acc[k] - __bfloat162float(hi);
        g_nuA_hi[base + k * 8] = hi;
        g_nuA_lo[base + k * 8] = __float2bfloat16(lo);
    }
}

// ---------------- pool = A @ nu_in via mma.sync bf16 (hi/lo) ----------------
// CTA tile 128(m) x 64(c). 8 warps (4Mx2N), 2 CTAs/SM.
// mode 0: epilogue computes mu in smem and emits next nu hi/lo into nu_out
//         (ping-pong buffer: disjoint from nu_in -> no cross-CTA WAR race).
// mode 1: epilogue writes g_mu + column-sum partials (final round).
__global__ __launch_bounds__(256, 2) void k_mma(int mode, const float* __restrict__ W2,
                                                const __nv_bfloat16* __restrict__ nin_hi,
                                                const __nv_bfloat16* __restrict__ nin_lo,
                                                __nv_bfloat16* __restrict__ nout_hi,
                                                __nv_bfloat16* __restrict__ nout_lo) {
    __shared__ __align__(16) char SB[49152];  // 0..32KB: stages / mu tile; 32..48KB: W2q

    int tid = threadIdx.x;
    int lane = tid & 31, wid = tid >> 5;
    int warpM = wid >> 1, warpN = wid & 1;   // 4 x 2 warps; warp tile 32(m) x 32(c)
    int mbase = blockIdx.y * 128;
    int cbase = blockIdx.x * 64;

    uint32_t sb0 = smem_u32(SB);
    uint32_t asb[2] = { sb0,          sb0 + 16384 };
    uint32_t bhb[2] = { sb0 + 8192,   sb0 + 24576 };
    uint32_t blb[2] = { sb0 + 12288,  sb0 + 28672 };
    float4* W2q = (float4*)(SB + 32768);

    float C[8][4];
#pragma unroll
    for (int i = 0; i < 8; i++)
#pragma unroll
        for (int j = 0; j < 4; j++) C[i][j] = 0.f;

    auto load_stage = [&](int ch, int buf) {
        // A: 128 rows x 32 k bf16 = 8KB -> 512 units, 2 per thread
#pragma unroll
        for (int t = 0; t < 2; t++) {
            int i = tid + t * 256;
            int m = i >> 2, u = i & 3;
            const __nv_bfloat16* g = g_Abf + (size_t)(mbase + m) * NN + ch * 32 + u * 8;
            uint32_t s = asb[buf] + m * 64 + (((u ^ ((m >> 1) & 3)) & 3) << 4);
            cp16(s, g);
        }
        // B: 32 k x 64 c bf16 = 4KB each -> 256 units, 1 per thread each
        {
            int k = tid >> 3, u = tid & 7;
            int su = (u ^ k) & 7;
            size_t go = (size_t)(ch * 32 + k) * CC + cbase + u * 8;
            uint32_t so = k * 128 + (su << 4);
            cp16(bhb[buf] + so, nin_hi + go);
            cp16(blb[buf] + so, nin_lo + go);
        }
        asm volatile("cp.async.commit_group;\n" ::: "memory");
    };

    load_stage(0, 0);

    // stage W2 into the spare 16KB while the first cp.async stage is in flight
    if (mode == 0) {
        for (int i = tid; i < 1024; i += 256) {
            int d = i >> 4, e4 = i & 15;
            W2q[e4 * 64 + d] = ((const float4*)(W2 + d * DD))[e4];
        }
    }

    for (int ch = 0; ch < 32; ch++) {
        int buf = ch & 1;
        if (ch + 1 < 32) load_stage(ch + 1, buf ^ 1);
        if (ch + 1 < 32) asm volatile("cp.async.wait_group 1;\n" ::: "memory");
        else             asm volatile("cp.async.wait_group 0;\n" ::: "memory");
        __syncthreads();

#pragma unroll
        for (int ks = 0; ks < 2; ks++) {
            uint32_t a[2][4];
#pragma unroll
            for (int mt = 0; mt < 2; mt++) {
                int row = warpM * 32 + mt * 16 + (lane & 7) + ((lane >> 3) & 1) * 8;
                int unit = 2 * ks + (lane >> 4);
                uint32_t addr = asb[buf] + row * 64 + (((unit ^ ((row >> 1) & 3)) & 3) << 4);
                asm volatile("ldmatrix.sync.aligned.m8n8.x4.shared.b16 {%0,%1,%2,%3}, [%4];"
                             : "=r"(a[mt][0]), "=r"(a[mt][1]), "=r"(a[mt][2]), "=r"(a[mt][3])
                             : "r"(addr));
            }
            uint32_t bhf[4][2], blf[4][2];
#pragma unroll
            for (int pair = 0; pair < 2; pair++) {
                int k = ks * 16 + (lane & 7) + ((lane >> 3) & 1) * 8;
                int u = warpN * 4 + pair * 2 + (lane >> 4);
                int su = (u ^ k) & 7;
                uint32_t so = k * 128 + (su << 4);
                asm volatile("ldmatrix.sync.aligned.m8n8.x4.trans.shared.b16 {%0,%1,%2,%3}, [%4];"
                             : "=r"(bhf[pair * 2][0]), "=r"(bhf[pair * 2][1]),
                               "=r"(bhf[pair * 2 + 1][0]), "=r"(bhf[pair * 2 + 1][1])
                             : "r"(bhb[buf] + so));
                asm volatile("ldmatrix.sync.aligned.m8n8.x4.trans.shared.b16 {%0,%1,%2,%3}, [%4];"
                             : "=r"(blf[pair * 2][0]), "=r"(blf[pair * 2][1]),
                               "=r"(blf[pair * 2 + 1][0]), "=r"(blf[pair * 2 + 1][1])
                             : "r"(blb[buf] + so));
            }
#pragma unroll
            for (int mt = 0; mt < 2; mt++) {
#pragma unroll
                for (int nt = 0; nt < 4; nt++) {
                    float* c = C[mt * 4 + nt];
                    asm volatile(
                        "mma.sync.aligned.m16n8k16.row.col.f32.bf16.bf16.f32 "
                        "{%0,%1,%2,%3},{%4,%5,%6,%7},{%8,%9},{%0,%1,%2,%3};"
                        : "+f"(c[0]), "+f"(c[1]), "+f"(c[2]), "+f"(c[3])
                        : "r"(a[mt][0]), "r"(a[mt][1]), "r"(a[mt][2]), "r"(a[mt][3]),
                          "r"(bhf[nt][0]), "r"(bhf[nt][1]));
                    asm volatile(
                        "mma.sync.aligned.m16n8k16.row.col.f32.bf16.bf16.f32 "
                        "{%0,%1,%2,%3},{%4,%5,%6,%7},{%8,%9},{%0,%1,%2,%3};"
                        : "+f"(c[0]), "+f"(c[1]), "+f"(c[2]), "+f"(c[3])
                        : "r"(a[mt][0]), "r"(a[mt][1]), "r"(a[mt][2]), "r"(a[mt][3]),
                          "r"(blf[nt][0]), "r"(blf[nt][1]));
                }
            }
        }
        __syncthreads();
    }

    int g = lane >> 2, tq = lane & 3;

    if (mode == 0) {
        // ---- epilogue: mu = relu(m13 + pool) into smem tile; emit next nu ----
        float* mt_s = (float*)SB;   // [128][64] fp32, overwrites stage buffers
#pragma unroll
        for (int mt = 0; mt < 2; mt++) {
#pragma unroll
            for (int nt = 0; nt < 4; nt++) {
                const float* c = C[mt * 4 + nt];
                int rl0 = warpM * 32 + mt * 16 + g;
                int cl = warpN * 32 + nt * 8 + tq * 2;
                {
                    const float2 m = *(const float2*)(g_m13 + (size_t)(mbase + rl0) * CC + cbase + cl);
                    mt_s[rl0 * 64 + cl]     = fmaxf(m.x + c[0], 0.f);
                    mt_s[rl0 * 64 + cl + 1] = fmaxf(m.y + c[1], 0.f);
                }
                {
                    int rl1 = rl0 + 8;
                    const float2 m = *(const float2*)(g_m13 + (size_t)(mbase + rl1) * CC + cbase + cl);
                    mt_s[rl1 * 64 + cl]     = fmaxf(m.x + c[2], 0.f);
                    mt_s[rl1 * 64 + cl + 1] = fmaxf(m.y + c[3], 0.f);
                }
            }
        }
        __syncthreads();

        // nu = mu @ W2^T: thread = (rowgroup of 4, dg); acc[4][8]
        int rg = tid >> 3, dg = tid & 7;
        float acc[4][8] = {};
        const float* r0 = mt_s + (rg * 4 + 0) * 64;
        const float* r1 = mt_s + (rg * 4 + 1) * 64;
        const float* r2 = mt_s + (rg * 4 + 2) * 64;
        const float* r3 = mt_s + (rg * 4 + 3) * 64;
#pragma unroll
        for (int e4 = 0; e4 < 16; e4++) {
            float4 m0 = ((const float4*)r0)[e4];
            float4 m1 = ((const float4*)r1)[e4];
            float4 m2 = ((const float4*)r2)[e4];
            float4 m3v = ((const float4*)r3)[e4];
#pragma unroll
            for (int k = 0; k < 8; k++) {
                float4 w = W2q[e4 * 64 + k * 8 + dg];
                acc[0][k] += m0.x * w.x + m0.y * w.y + m0.z * w.z + m0.w * w.w;
                acc[1][k] += m1.x * w.x + m1.y * w.y + m1.z * w.z + m1.w * w.w;
                acc[2][k] += m2.x * w.x + m2.y * w.y + m2.z * w.z + m2.w * w.w;
                acc[3][k] += m3v.x * w.x + m3v.y * w.y + m3v.z * w.z + m3v.w * w.w;
            }
        }
#pragma unroll
        for (int j = 0; j < 4; j++) {
            size_t base = (size_t)(mbase + rg * 4 + j) * CC + cbase + dg;
#pragma unroll
            for (int k = 0; k < 8; k++) {
                float a = acc[j][k];
                __nv_bfloat16 hi = __float2bfloat16(a);
                float lo = a - __bfloat162float(hi);
                nout_hi[base + k * 8] = hi;
                nout_lo[base + k * 8] = __float2bfloat16(lo);
            }
        }
    } else {
        // ---- final round: mu -> global, plus column-sum partials ----
#pragma unroll
        for (int mt = 0; mt < 2; mt++) {
#pragma unroll
            for (int nt = 0; nt < 4; nt++) {
                const float* c = C[mt * 4 + nt];
                int row0 = mbase + warpM * 32 + mt * 16 + g;
                int col = cbase + warpN * 32 + nt * 8 + tq * 2;
                {
                    const float2 m = *(const float2*)(g_m13 + (size_t)row0 * CC + col);
                    float2 o;
                    o.x = fmaxf(m.x + c[0], 0.f);
                    o.y = fmaxf(m.y + c[1], 0.f);
                    *(float2*)(g_mu + (size_t)row0 * CC + col) = o;
                }
                {
                    int row1 = row0 + 8;
                    const float2 m = *(const float2*)(g_m13 + (size_t)row1 * CC + col);
                    float2 o;
                    o.x = fmaxf(m.x + c[2], 0.f);
                    o.y = fmaxf(m.y + c[3], 0.f);
                    *(float2*)(g_mu + (size_t)row1 * CC + col) = o;
                }
            }
        }
        float* cs = (float*)SB;
        __syncthreads();
        int c = tid & 63, q = tid >> 6;
        const float* mp = g_mu + (size_t)(mbase + q * 32) * CC + cbase + c;
        float s = 0.f;
#pragma unroll 8
        for (int r = 0; r < 32; r++) s += mp[(size_t)r * CC];
        cs[q * 64 + c] = s;
        __syncthreads();
        if (tid < 64)
            g_part[blockIdx.y * CC + cbase + tid] =
                cs[tid] + cs[64 + tid] + cs[128 + tid] + cs[192 + tid];
    }
}

// ---------------- mumean + s2, one block per b ----------------
__global__ __launch_bounds__(64) void k_small(const float* __restrict__ option,
                                              const float* __restrict__ Wq1,
                                              const float* __restrict__ bq1,
                                              const float* __restrict__ Wq2,
                                              const float* __restrict__ bq2,
                                              const float* __restrict__ Wreg) {
    int b = blockIdx.x, d = threadIdx.x;
    __shared__ float msum[DD];
    float s = 0.f;
#pragma unroll
    for (int g = 0; g < 8; g++) s += g_part[g * CC + b * DD + d];
    msum[d] = s * (1.0f / (float)NN);
    __syncthreads();
    float acc = bq1[d];
#pragma unroll
    for (int e = 0; e < DD; e++) acc += msum[e] * Wq1[d * DD + e];
    g_mumean[b * DD + d] = fmaxf(acc, 0.f);
    float opt = option[b];
    float acc2 = 0.f;
#pragma unroll
    for (int j = 0; j < DD; j++)
        acc2 += (opt * Wq2[j] + bq2[j]) * Wreg[d * (2 * DD) + DD + j];
    g_s2[b * HH + d] = acc2;
}

// ---------------- final head ----------------
__global__ __launch_bounds__(256) void k_final(const float* __restrict__ Wreg,
                                               const float* __restrict__ breg,
                                               const float* __restrict__ Wq,
                                               const float* __restrict__ bq,
                                               float* __restrict__ out) {
    int b = blockIdx.y;
    int tile = blockIdx.x;
    __shared__ float Wr[HH][DD + 1];
    __shared__ float wqs[HH], s2s[HH], brs[HH];
    __shared__ float vs[8][DD];
    int tid = threadIdx.x;
    for (int i = tid; i < HH * DD; i += 256) {
        int h = i >> 6, j = i & 63;
        Wr[h][j] = Wreg[h * (2 * DD) + j];
    }
    if (tid < HH) {
        wqs[tid] = Wq[tid];
        s2s[tid] = g_s2[b * HH + tid];
        brs[tid] = breg[tid];
    }
    __syncthreads();
    int w = tid >> 5, lane = tid & 31;
    float bqv = bq[0];
    for (int s = 0; s < 8; s++) {
        int i = tile * 64 + w * 8 + s;
        if (i > NN) continue;
        const float* vptr = (i < NN) ? (g_mu + (size_t)i * CC + b * DD) : (g_mumean + b * DD);
        vs[w][lane]      = vptr[lane];
        vs[w][lane + 32] = vptr[lane + 32];
        __syncwarp();
        float r = 0.f;
#pragma unroll
        for (int hh = 0; hh < 2; hh++) {
            int h = lane + hh * 32;
            float accd = s2s[h] + brs[h];
#pragma unroll
            for (int j = 0; j < DD; j++) accd += vs[w][j] * Wr[h][j];
            r += fmaxf(accd, 0.f) * wqs[h];
        }
#pragma unroll
        for (int off = 16; off; off >>= 1) r += __shfl_down_sync(0xffffffff, r, off);
        if (lane == 0) out[b * NP1 + i] = r + bqv;
        __syncwarp();
    }
}

// ---------------- launch ----------------
extern "C" void kernel_launch(void* const* d_in, const int* in_sizes, int n_in,
                              void* d_out, int out_size) {
    const float* xv     = (const float*)d_in[0];
    const float* option = (const float*)d_in[1];
    const float* adj    = (const float*)d_in[2];
    const float* mu1w   = (const float*)d_in[3];
    const float* W2     = (const float*)d_in[4];
    const float* b2     = (const float*)d_in[5];
    const float* W3     = (const float*)d_in[6];
    const float* b3     = (const float*)d_in[7];
    const float* W4     = (const float*)d_in[8];
    const float* b4     = (const float*)d_in[9];
    const float* Wq1    = (const float*)d_in[10];
    const float* bq1    = (const float*)d_in[11];
    const float* Wq2    = (const float*)d_in[12];
    const float* bq2    = (const float*)d_in[13];
    const float* Wreg   = (const float*)d_in[14];
    const float* breg   = (const float*)d_in[15];
    const float* Wq     = (const float*)d_in[16];
    const float* bq     = (const float*)d_in[17];
    float* out = (float*)d_out;
    (void)in_sizes; (void)n_in; (void)out_size;

    // device-symbol addresses for ping-pong nu buffers (no cudaGetSymbolAddress:
    // __device__ arrays are directly addressable from host-side kernel args via
    // taking their address in device code only — so pass via small launches).
    // Simpler: use the symbols directly in a tiny wrapper — but kernel params
    // must be host values. Use cudaGetSymbolAddress (allowed: no alloc).
    static __nv_bfloat16 *nuA_hi = nullptr, *nuA_lo = nullptr, *nuB_hi = nullptr, *nuB_lo = nullptr;
    if (!nuA_hi) {
        cudaGetSymbolAddress((void**)&nuA_hi, g_nuA_hi);
        cudaGetSymbolAddress((void**)&nuA_lo, g_nuA_lo);
        cudaGetSymbolAddress((void**)&nuB_hi, g_nuB_hi);
        cudaGetSymbolAddress((void**)&nuB_lo, g_nuB_lo);
    }

    k_graph<<<NN, 256>>>(adj, W4, b4, W3, b3);
    k_mu1<<<NN, 256>>>(xv, mu1w, b2, W2);
    k_mma<<<dim3(CC / 64, NN / 128), 256>>>(0, W2, nuA_hi, nuA_lo, nuB_hi, nuB_lo);  // t=1: A->B
    k_mma<<<dim3(CC / 64, NN / 128), 256>>>(0, W2, nuB_hi, nuB_lo, nuA_hi, nuA_lo);  // t=2: B->A
    k_mma<<<dim3(CC / 64, NN / 128), 256>>>(1, W2, nuA_hi, nuA_lo, nullptr, nullptr); // t=3
    k_small<<<32, 64>>>(option, Wq1, bq1, Wq2, bq2, Wreg);
    k_final<<<dim3(17, BB), 256>>>(Wreg, breg, Wq, bq, out);
}

// round 11
// speedup vs baseline: 1.6234x; 1.1345x over previous
#include <cuda_runtime.h>
#include <cuda_fp16.h>
#include <cstdint>

#define NN 1024
#define BB 32
#define FF 32
#define DD 64
#define HH 64
#define CC 2048   // B*D
#define NP1 1025

// ---------------- scratch (static __device__, no allocs) ----------------
__device__ __half g_Ah[NN * NN];      // binarized adjacency, fp16 (exact 0/1)
__device__ float g_m13[NN * CC];      // mu_1 + mu3 + b2
__device__ float g_mu[NN * CC];       // final-round mu (fp32)
__device__ __half g_nuA[NN * CC];     // nu ping buffer (fp16)
__device__ __half g_nuB[NN * CC];     // nu pong buffer (fp16)
__device__ float g_part[8 * CC];      // column-sum partials (per 128-row mtile)
__device__ float g_mumean[BB * DD];
__device__ float g_s2[BB * HH];

// ---------------- helpers ----------------
__device__ __forceinline__ uint32_t smem_u32(const void* p) {
    uint32_t a;
    asm("{ .reg .u64 t; cvta.to.shared.u64 t, %1; cvt.u32.u64 %0, t; }" : "=r"(a) : "l"(p));
    return a;
}
__device__ __forceinline__ void cp16(uint32_t saddr, const void* gaddr) {
    asm volatile("cp.async.cg.shared.global [%0], [%1], 16;\n" :: "r"(saddr), "l"(gaddr));
}

// ---------------- init: binarize adj + mu3 + mu_1 + m13 + first nu ----------------
__global__ __launch_bounds__(256) void k_init(const float* __restrict__ adj,
                                              const float* __restrict__ W4,
                                              const float* __restrict__ b4,
                                              const float* __restrict__ W3,
                                              const float* __restrict__ b3,
                                              const float* __restrict__ xv,
                                              const float* __restrict__ mu1w,
                                              const float* __restrict__ b2,
                                              const float* __restrict__ W2) {
    int n = blockIdx.x;
    int tid = threadIdx.x;
    __shared__ float arow[NN];
    __shared__ float part[4][DD];
    __shared__ float mu4s[DD];
    __shared__ float xs[BB][FF];
    __shared__ float ws[FF][DD];
    __shared__ float m3[DD];
    __shared__ float mus[CC];
    __shared__ float4 W2q[16 * 64];   // [e4][d]

    // adjacency row: raw to smem, binarized fp16 to global
    {
        float4 v = ((const float4*)(adj + (size_t)n * NN))[tid];
        arow[tid * 4 + 0] = v.x;
        arow[tid * 4 + 1] = v.y;
        arow[tid * 4 + 2] = v.z;
        arow[tid * 4 + 3] = v.w;
        union { uint2 u; __half h[4]; } pk;
        pk.h[0] = __float2half(v.x > 0.f ? 1.f : 0.f);
        pk.h[1] = __float2half(v.y > 0.f ? 1.f : 0.f);
        pk.h[2] = __float2half(v.z > 0.f ? 1.f : 0.f);
        pk.h[3] = __float2half(v.w > 0.f ? 1.f : 0.f);
        *(uint2*)(g_Ah + (size_t)n * NN + tid * 4) = pk.u;
    }
    // independent staging
    for (int i = tid; i < BB * FF; i += 256) {
        int b = i / FF, f = i % FF;
        xs[b][f] = xv[(b * NN + n) * FF + f];
    }
    for (int i = tid; i < FF * DD; i += 256) ws[i / DD][i % DD] = mu1w[i];
    for (int i = tid; i < 1024; i += 256) {
        int d = i >> 4, e4 = i & 15;
        W2q[e4 * 64 + d] = ((const float4*)(W2 + d * DD))[e4];
    }
    __syncthreads();

    // mu4 = sum_m relu(adj[n,m]*W4 + b4)
    {
        int d = tid & 63, q = tid >> 6;
        float w = W4[d], c0 = b4[d];
        float acc = 0.f;
        for (int m = q; m < NN; m += 4)
            acc += fmaxf(arow[m] * w + c0, 0.f);
        part[q][d] = acc;
    }
    __syncthreads();
    if (tid < DD) mu4s[tid] = part[0][tid] + part[1][tid] + part[2][tid] + part[3][tid];
    __syncthreads();
    if (tid < DD) {
        int d2 = tid;
        float a = b3[d2] + b2[d2];
#pragma unroll
        for (int e = 0; e < DD; e++) a += mu4s[e] * W3[d2 * DD + e];
        m3[d2] = a;   // mu3 + b3 + b2
    }
    __syncthreads();

    // mu_1 = relu(xv @ mu1); m13 = mu_1 + m3
#pragma unroll
    for (int j = 0; j < 8; j++) {
        int c = tid + 256 * j;
        int b = c >> 6, d = c & 63;
        float acc = 0.f;
#pragma unroll
        for (int f = 0; f < FF; f++) acc += xs[b][f] * ws[f][d];
        float r = fmaxf(acc, 0.f);
        g_m13[n * CC + c] = r + m3[d];
        mus[c] = r;
    }
    __syncthreads();

    // nu = mu @ W2^T -> nuA (fp16)
    int b = tid >> 3, dg = tid & 7;
    const float4* mb = (const float4*)(mus + b * DD);
    float acc[8] = {};
#pragma unroll
    for (int e4 = 0; e4 < 16; e4++) {
        float4 m = mb[e4];
#pragma unroll
        for (int k = 0; k < 8; k++) {
            float4 w = W2q[e4 * 64 + k * 8 + dg];
            acc[k] += m.x * w.x + m.y * w.y + m.z * w.z + m.w * w.w;
        }
    }
    size_t base = (size_t)n * CC + b * DD + dg;
#pragma unroll
    for (int k = 0; k < 8; k++)
        g_nuA[base + k * 8] = __float2half(acc[k]);
}

// ---------------- pool = A @ nu via mma.sync fp16; 3-stage cp.async pipeline ----------------
// CTA tile 128(m) x 64(c). 8 warps (4Mx2N), 2 CTAs/SM.
// mode 0: epilogue computes mu in smem, emits next nu (fp16) into nout (ping-pong).
// mode 1: epilogue writes g_mu + column-sum partials (final round).
__global__ __launch_bounds__(256, 2) void k_mma(int mode, const float* __restrict__ W2,
                                                const __half* __restrict__ nin,
                                                __half* __restrict__ nout) {
    __shared__ __align__(16) char SB[49152];  // stages: 3 x 12KB at 0/12288/24576

    int tid = threadIdx.x;
    int lane = tid & 31, wid = tid >> 5;
    int warpM = wid >> 1, warpN = wid & 1;   // 4 x 2 warps; warp tile 32(m) x 32(c)
    int mbase = blockIdx.y * 128;
    int cbase = blockIdx.x * 64;

    uint32_t sb0 = smem_u32(SB);
    uint32_t asb[3] = { sb0, sb0 + 12288, sb0 + 24576 };         // A: 8KB
    uint32_t bsb[3] = { sb0 + 8192, sb0 + 20480, sb0 + 32768 };  // B: 4KB

    float C[8][4];
#pragma unroll
    for (int i = 0; i < 8; i++)
#pragma unroll
        for (int j = 0; j < 4; j++) C[i][j] = 0.f;

    auto load_stage = [&](int ch, int buf) {
        // A: 128 rows x 32 k fp16 = 8KB -> 512 units, 2 per thread
#pragma unroll
        for (int t = 0; t < 2; t++) {
            int i = tid + t * 256;
            int m = i >> 2, u = i & 3;
            const __half* g = g_Ah + (size_t)(mbase + m) * NN + ch * 32 + u * 8;
            uint32_t s = asb[buf] + m * 64 + (((u ^ ((m >> 1) & 3)) & 3) << 4);
            cp16(s, g);
        }
        // B: 32 k x 64 c fp16 = 4KB -> 256 units, 1 per thread
        {
            int k = tid >> 3, u = tid & 7;
            int su = (u ^ k) & 7;
            size_t go = (size_t)(ch * 32 + k) * CC + cbase + u * 8;
            uint32_t so = k * 128 + (su << 4);
            cp16(bsb[buf] + so, nin + go);
        }
        asm volatile("cp.async.commit_group;\n" ::: "memory");
    };

    load_stage(0, 0);
    load_stage(1, 1);

    for (int ch = 0; ch < 32; ch++) {
        int buf = ch % 3;
        if (ch + 2 < 32) {
            load_stage(ch + 2, (ch + 2) % 3);
            asm volatile("cp.async.wait_group 2;\n" ::: "memory");
        } else if (ch + 1 < 32) {
            asm volatile("cp.async.wait_group 1;\n" ::: "memory");
        } else {
            asm volatile("cp.async.wait_group 0;\n" ::: "memory");
        }
        __syncthreads();

#pragma unroll
        for (int ks = 0; ks < 2; ks++) {
            uint32_t a[2][4];
#pragma unroll
            for (int mt = 0; mt < 2; mt++) {
                int row = warpM * 32 + mt * 16 + (lane & 7) + ((lane >> 3) & 1) * 8;
                int unit = 2 * ks + (lane >> 4);
                uint32_t addr = asb[buf] + row * 64 + (((unit ^ ((row >> 1) & 3)) & 3) << 4);
                asm volatile("ldmatrix.sync.aligned.m8n8.x4.shared.b16 {%0,%1,%2,%3}, [%4];"
                             : "=r"(a[mt][0]), "=r"(a[mt][1]), "=r"(a[mt][2]), "=r"(a[mt][3])
                             : "r"(addr));
            }
            uint32_t bf[4][2];
#pragma unroll
            for (int pair = 0; pair < 2; pair++) {
                int k = ks * 16 + (lane & 7) + ((lane >> 3) & 1) * 8;
                int u = warpN * 4 + pair * 2 + (lane >> 4);
                int su = (u ^ k) & 7;
                uint32_t so = k * 128 + (su << 4);
                asm volatile("ldmatrix.sync.aligned.m8n8.x4.trans.shared.b16 {%0,%1,%2,%3}, [%4];"
                             : "=r"(bf[pair * 2][0]), "=r"(bf[pair * 2][1]),
                               "=r"(bf[pair * 2 + 1][0]), "=r"(bf[pair * 2 + 1][1])
                             : "r"(bsb[buf] + so));
            }
#pragma unroll
            for (int mt = 0; mt < 2; mt++) {
#pragma unroll
                for (int nt = 0; nt < 4; nt++) {
                    float* c = C[mt * 4 + nt];
                    asm volatile(
                        "mma.sync.aligned.m16n8k16.row.col.f32.f16.f16.f32 "
                        "{%0,%1,%2,%3},{%4,%5,%6,%7},{%8,%9},{%0,%1,%2,%3};"
                        : "+f"(c[0]), "+f"(c[1]), "+f"(c[2]), "+f"(c[3])
                        : "r"(a[mt][0]), "r"(a[mt][1]), "r"(a[mt][2]), "r"(a[mt][3]),
                          "r"(bf[nt][0]), "r"(bf[nt][1]));
                }
            }
        }
        __syncthreads();
    }

    int g = lane >> 2, tq = lane & 3;

    if (mode == 0) {
        // ---- epilogue: mu = relu(m13 + pool) into smem; emit next nu (fp16) ----
        float* mt_s = (float*)SB;                 // [128][64] fp32 = 32KB
        float4* W2q = (float4*)(SB + 32768);      // 16KB
        for (int i = tid; i < 1024; i += 256) {
            int d = i >> 4, e4 = i & 15;
            W2q[e4 * 64 + d] = ((const float4*)(W2 + d * DD))[e4];
        }
#pragma unroll
        for (int mt = 0; mt < 2; mt++) {
#pragma unroll
            for (int nt = 0; nt < 4; nt++) {
                const float* c = C[mt * 4 + nt];
                int rl0 = warpM * 32 + mt * 16 + g;
                int cl = warpN * 32 + nt * 8 + tq * 2;
                {
                    const float2 m = *(const float2*)(g_m13 + (size_t)(mbase + rl0) * CC + cbase + cl);
                    mt_s[rl0 * 64 + cl]     = fmaxf(m.x + c[0], 0.f);
                    mt_s[rl0 * 64 + cl + 1] = fmaxf(m.y + c[1], 0.f);
                }
                {
                    int rl1 = rl0 + 8;
                    const float2 m = *(const float2*)(g_m13 + (size_t)(mbase + rl1) * CC + cbase + cl);
                    mt_s[rl1 * 64 + cl]     = fmaxf(m.x + c[2], 0.f);
                    mt_s[rl1 * 64 + cl + 1] = fmaxf(m.y + c[3], 0.f);
                }
            }
        }
        __syncthreads();

        // nu = mu @ W2^T: thread = (rowgroup of 4, dg); acc[4][8]
        int rg = tid >> 3, dg = tid & 7;
        float acc[4][8] = {};
        const float* r0 = mt_s + (rg * 4 + 0) * 64;
        const float* r1 = mt_s + (rg * 4 + 1) * 64;
        const float* r2 = mt_s + (rg * 4 + 2) * 64;
        const float* r3 = mt_s + (rg * 4 + 3) * 64;
#pragma unroll
        for (int e4 = 0; e4 < 16; e4++) {
            float4 m0 = ((const float4*)r0)[e4];
            float4 m1 = ((const float4*)r1)[e4];
            float4 m2 = ((const float4*)r2)[e4];
            float4 m3v = ((const float4*)r3)[e4];
#pragma unroll
            for (int k = 0; k < 8; k++) {
                float4 w = W2q[e4 * 64 + k * 8 + dg];
                acc[0][k] += m0.x * w.x + m0.y * w.y + m0.z * w.z + m0.w * w.w;
                acc[1][k] += m1.x * w.x + m1.y * w.y + m1.z * w.z + m1.w * w.w;
                acc[2][k] += m2.x * w.x + m2.y * w.y + m2.z * w.z + m2.w * w.w;
                acc[3][k] += m3v.x * w.x + m3v.y * w.y + m3v.z * w.z + m3v.w * w.w;
            }
        }
#pragma unroll
        for (int j = 0; j < 4; j++) {
            size_t base = (size_t)(mbase + rg * 4 + j) * CC + cbase + dg;
#pragma unroll
            for (int k = 0; k < 8; k++)
                nout[base + k * 8] = __float2half(acc[j][k]);
        }
    } else {
        // ---- final round: mu -> global, plus column-sum partials ----
#pragma unroll
        for (int mt = 0; mt < 2; mt++) {
#pragma unroll
            for (int nt = 0; nt < 4; nt++) {
                const float* c = C[mt * 4 + nt];
                int row0 = mbase + warpM * 32 + mt * 16 + g;
                int col = cbase + warpN * 32 + nt * 8 + tq * 2;
                {
                    const float2 m = *(const float2*)(g_m13 + (size_t)row0 * CC + col);
                    float2 o;
                    o.x = fmaxf(m.x + c[0], 0.f);
                    o.y = fmaxf(m.y + c[1], 0.f);
                    *(float2*)(g_mu + (size_t)row0 * CC + col) = o;
                }
                {
                    int row1 = row0 + 8;
                    const float2 m = *(const float2*)(g_m13 + (size_t)row1 * CC + col);
                    float2 o;
                    o.x = fmaxf(m.x + c[2], 0.f);
                    o.y = fmaxf(m.y + c[3], 0.f);
                    *(float2*)(g_mu + (size_t)row1 * CC + col) = o;
                }
            }
        }
        float* cs = (float*)SB;
        __syncthreads();
        int c = tid & 63, q = tid >> 6;
        const float* mp = g_mu + (size_t)(mbase + q * 32) * CC + cbase + c;
        float s = 0.f;
#pragma unroll 8
        for (int r = 0; r < 32; r++) s += mp[(size_t)r * CC];
        cs[q * 64 + c] = s;
        __syncthreads();
        if (tid < 64)
            g_part[blockIdx.y * CC + cbase + tid] =
                cs[tid] + cs[64 + tid] + cs[128 + tid] + cs[192 + tid];
    }
}

// ---------------- mumean + s2, one block per b ----------------
__global__ __launch_bounds__(64) void k_small(const float* __restrict__ option,
                                              const float* __restrict__ Wq1,
                                              const float* __restrict__ bq1,
                                              const float* __restrict__ Wq2,
                                              const float* __restrict__ bq2,
                                              const float* __restrict__ Wreg) {
    int b = blockIdx.x, d = threadIdx.x;
    __shared__ float msum[DD];
    float s = 0.f;
#pragma unroll
    for (int g = 0; g < 8; g++) s += g_part[g * CC + b * DD + d];
    msum[d] = s * (1.0f / (float)NN);
    __syncthreads();
    float acc = bq1[d];
#pragma unroll
    for (int e = 0; e < DD; e++) acc += msum[e] * Wq1[d * DD + e];
    g_mumean[b * DD + d] = fmaxf(acc, 0.f);
    float opt = option[b];
    float acc2 = 0.f;
#pragma unroll
    for (int j = 0; j < DD; j++)
        acc2 += (opt * Wq2[j] + bq2[j]) * Wreg[d * (2 * DD) + DD + j];
    g_s2[b * HH + d] = acc2;
}

// ---------------- final head ----------------
__global__ __launch_bounds__(256) void k_final(const float* __restrict__ Wreg,
                                               const float* __restrict__ breg,
                                               const float* __restrict__ Wq,
                                               const float* __restrict__ bq,
                                               float* __restrict__ out) {
    int b = blockIdx.y;
    int tile = blockIdx.x;
    __shared__ float Wr[HH][DD + 1];
    __shared__ float wqs[HH], s2s[HH], brs[HH];
    __shared__ float vs[8][DD];
    int tid = threadIdx.x;
    for (int i = tid; i < HH * DD; i += 256) {
        int h = i >> 6, j = i & 63;
        Wr[h][j] = Wreg[h * (2 * DD) + j];
    }
    if (tid < HH) {
        wqs[tid] = Wq[tid];
        s2s[tid] = g_s2[b * HH + tid];
        brs[tid] = breg[tid];
    }
    __syncthreads();
    int w = tid >> 5, lane = tid & 31;
    float bqv = bq[0];
    for (int s = 0; s < 8; s++) {
        int i = tile * 64 + w * 8 + s;
        if (i > NN) continue;
        const float* vptr = (i < NN) ? (g_mu + (size_t)i * CC + b * DD) : (g_mumean + b * DD);
        vs[w][lane]      = vptr[lane];
        vs[w][lane + 32] = vptr[lane + 32];
        __syncwarp();
        float r = 0.f;
#pragma unroll
        for (int hh = 0; hh < 2; hh++) {
            int h = lane + hh * 32;
            float accd = s2s[h] + brs[h];
#pragma unroll
            for (int j = 0; j < DD; j++) accd += vs[w][j] * Wr[h][j];
            r += fmaxf(accd, 0.f) * wqs[h];
        }
#pragma unroll
        for (int off = 16; off; off >>= 1) r += __shfl_down_sync(0xffffffff, r, off);
        if (lane == 0) out[b * NP1 + i] = r + bqv;
        __syncwarp();
    }
}

// ---------------- launch ----------------
extern "C" void kernel_launch(void* const* d_in, const int* in_sizes, int n_in,
                              void* d_out, int out_size) {
    const float* xv     = (const float*)d_in[0];
    const float* option = (const float*)d_in[1];
    const float* adj    = (const float*)d_in[2];
    const float* mu1w   = (const float*)d_in[3];
    const float* W2     = (const float*)d_in[4];
    const float* b2     = (const float*)d_in[5];
    const float* W3     = (const float*)d_in[6];
    const float* b3     = (const float*)d_in[7];
    const float* W4     = (const float*)d_in[8];
    const float* b4     = (const float*)d_in[9];
    const float* Wq1    = (const float*)d_in[10];
    const float* bq1    = (const float*)d_in[11];
    const float* Wq2    = (const float*)d_in[12];
    const float* bq2    = (const float*)d_in[13];
    const float* Wreg   = (const float*)d_in[14];
    const float* breg   = (const float*)d_in[15];
    const float* Wq     = (const float*)d_in[16];
    const float* bq     = (const float*)d_in[17];
    float* out = (float*)d_out;
    (void)in_sizes; (void)n_in; (void)out_size;

    static __half *nuA = nullptr, *nuB = nullptr;
    if (!nuA) {
        cudaGetSymbolAddress((void**)&nuA, g_nuA);
        cudaGetSymbolAddress((void**)&nuB, g_nuB);
    }

    k_init<<<NN, 256>>>(adj, W4, b4, W3, b3, xv, mu1w, b2, W2);
    k_mma<<<dim3(CC / 64, NN / 128), 256>>>(0, W2, nuA, nuB);   // t=1: A->B
    k_mma<<<dim3(CC / 64, NN / 128), 256>>>(0, W2, nuB, nuA);   // t=2: B->A
    k_mma<<<dim3(CC / 64, NN / 128), 256>>>(1, W2, nuA, nullptr); // t=3
    k_small<<<32, 64>>>(option, Wq1, bq1, Wq2, bq2, Wreg);
    k_final<<<dim3(17, BB), 256>>>(Wreg, breg, Wq, bq, out);
}

// round 12
// speedup vs baseline: 1.7052x; 1.0504x over previous
#include <cuda_runtime.h>
#include <cuda_fp16.h>
#include <cstdint>

#define NN 1024
#define BB 32
#define FF 32
#define DD 64
#define HH 64
#define CC 2048   // B*D
#define NP1 1025

// ---------------- scratch (static __device__, no allocs) ----------------
__device__ __half g_Ah[NN * NN];      // binarized adjacency, fp16 (exact 0/1)
__device__ float g_m13[NN * CC];      // mu_1 + mu3 + b2
__device__ float g_mu[NN * CC];       // final-round mu (fp32)
__device__ __half g_nuA[NN * CC];     // nu ping buffer (fp16)
__device__ __half g_nuB[NN * CC];     // nu pong buffer (fp16)
__device__ float g_part[8 * CC];      // column-sum partials (per 128-row mtile)
__device__ float g_mumean[BB * DD];
__device__ float g_s2[BB * HH];

// ---------------- helpers ----------------
__device__ __forceinline__ uint32_t smem_u32(const void* p) {
    uint32_t a;
    asm("{ .reg .u64 t; cvta.to.shared.u64 t, %1; cvt.u32.u64 %0, t; }" : "=r"(a) : "l"(p));
    return a;
}
__device__ __forceinline__ void cp16(uint32_t saddr, const void* gaddr) {
    asm volatile("cp.async.cg.shared.global [%0], [%1], 16;\n" :: "r"(saddr), "l"(gaddr));
}

// ---------------- init: binarize adj + mu3 + mu_1 + m13 + first nu ----------------
__global__ __launch_bounds__(256) void k_init(const float* __restrict__ adj,
                                              const float* __restrict__ W4,
                                              const float* __restrict__ b4,
                                              const float* __restrict__ W3,
                                              const float* __restrict__ b3,
                                              const float* __restrict__ xv,
                                              const float* __restrict__ mu1w,
                                              const float* __restrict__ b2,
                                              const float* __restrict__ W2) {
    int n = blockIdx.x;
    int tid = threadIdx.x;
    __shared__ float arow[NN];
    __shared__ float part[4][DD];
    __shared__ float mu4s[DD];
    __shared__ float xs[BB][FF];
    __shared__ float ws[FF][DD];
    __shared__ float m3[DD];
    __shared__ float mus[CC];
    __shared__ float4 W2q[16 * 64];   // [e4][d]

    // adjacency row: raw to smem, binarized fp16 to global
    {
        float4 v = ((const float4*)(adj + (size_t)n * NN))[tid];
        arow[tid * 4 + 0] = v.x;
        arow[tid * 4 + 1] = v.y;
        arow[tid * 4 + 2] = v.z;
        arow[tid * 4 + 3] = v.w;
        union { uint2 u; __half h[4]; } pk;
        pk.h[0] = __float2half(v.x > 0.f ? 1.f : 0.f);
        pk.h[1] = __float2half(v.y > 0.f ? 1.f : 0.f);
        pk.h[2] = __float2half(v.z > 0.f ? 1.f : 0.f);
        pk.h[3] = __float2half(v.w > 0.f ? 1.f : 0.f);
        *(uint2*)(g_Ah + (size_t)n * NN + tid * 4) = pk.u;
    }
    for (int i = tid; i < BB * FF; i += 256) {
        int b = i / FF, f = i % FF;
        xs[b][f] = xv[(b * NN + n) * FF + f];
    }
    for (int i = tid; i < FF * DD; i += 256) ws[i / DD][i % DD] = mu1w[i];
    for (int i = tid; i < 1024; i += 256) {
        int d = i >> 4, e4 = i & 15;
        W2q[e4 * 64 + d] = ((const float4*)(W2 + d * DD))[e4];
    }
    __syncthreads();

    // mu4 = sum_m relu(adj[n,m]*W4 + b4) — 4 independent accumulators
    {
        int d = tid & 63, q = tid >> 6;
        float w = W4[d], c0 = b4[d];
        float a0 = 0.f, a1 = 0.f, a2 = 0.f, a3 = 0.f;
        for (int m = q; m < NN; m += 16) {
            a0 += fmaxf(arow[m]      * w + c0, 0.f);
            a1 += fmaxf(arow[m + 4]  * w + c0, 0.f);
            a2 += fmaxf(arow[m + 8]  * w + c0, 0.f);
            a3 += fmaxf(arow[m + 12] * w + c0, 0.f);
        }
        part[q][d] = (a0 + a1) + (a2 + a3);
    }
    __syncthreads();
    if (tid < DD) mu4s[tid] = part[0][tid] + part[1][tid] + part[2][tid] + part[3][tid];
    __syncthreads();
    // mu3 GEMV over all 256 threads: thread (q2, d2) sums 16 e's
    {
        int d2 = tid & 63, q2 = tid >> 6;
        float a = 0.f;
#pragma unroll
        for (int e = 0; e < 16; e++)
            a += mu4s[q2 * 16 + e] * W3[d2 * DD + q2 * 16 + e];
        part[q2][d2] = a;
    }
    __syncthreads();
    if (tid < DD)
        m3[tid] = b3[tid] + b2[tid] + part[0][tid] + part[1][tid] + part[2][tid] + part[3][tid];
    __syncthreads();

    // mu_1 = relu(xv @ mu1); m13 = mu_1 + m3
#pragma unroll
    for (int j = 0; j < 8; j++) {
        int c = tid + 256 * j;
        int b = c >> 6, d = c & 63;
        float acc = 0.f;
#pragma unroll
        for (int f = 0; f < FF; f++) acc += xs[b][f] * ws[f][d];
        float r = fmaxf(acc, 0.f);
        g_m13[n * CC + c] = r + m3[d];
        mus[c] = r;
    }
    __syncthreads();

    // nu = mu @ W2^T -> nuA (fp16)
    int b = tid >> 3, dg = tid & 7;
    const float4* mb = (const float4*)(mus + b * DD);
    float acc[8] = {};
#pragma unroll
    for (int e4 = 0; e4 < 16; e4++) {
        float4 m = mb[e4];
#pragma unroll
        for (int k = 0; k < 8; k++) {
            float4 w = W2q[e4 * 64 + k * 8 + dg];
            acc[k] += m.x * w.x + m.y * w.y + m.z * w.z + m.w * w.w;
        }
    }
    size_t base = (size_t)n * CC + b * DD + dg;
#pragma unroll
    for (int k = 0; k < 8; k++)
        g_nuA[base + k * 8] = __float2half(acc[k]);
}

// ---------------- pool = A @ nu via mma.sync fp16; 3-stage cp.async pipeline ----------------
// CTA tile 128(m) x 64(c). 8 warps (4Mx2N), 2 CTAs/SM.
// mode 0: epilogue computes mu in smem, emits next nu (fp16) into nout (ping-pong).
// mode 1: epilogue writes g_mu + column-sum partials (final round).
__global__ __launch_bounds__(256, 2) void k_mma(int mode, const float* __restrict__ W2,
                                                const __half* __restrict__ nin,
                                                __half* __restrict__ nout) {
    __shared__ __align__(16) char SB[49152];  // stages: 3 x 12KB at 0/12288/24576

    int tid = threadIdx.x;
    int lane = tid & 31, wid = tid >> 5;
    int warpM = wid >> 1, warpN = wid & 1;   // 4 x 2 warps; warp tile 32(m) x 32(c)
    int mbase = blockIdx.y * 128;
    int cbase = blockIdx.x * 64;

    uint32_t sb0 = smem_u32(SB);
    uint32_t asb[3] = { sb0, sb0 + 12288, sb0 + 24576 };         // A: 8KB
    uint32_t bsb[3] = { sb0 + 8192, sb0 + 20480, sb0 + 32768 };  // B: 4KB

    // hoisted ldmatrix offsets (loop-invariant swizzle math)
    uint32_t aoff[2][2], boff[2][2];
#pragma unroll
    for (int ks = 0; ks < 2; ks++) {
#pragma unroll
        for (int mt = 0; mt < 2; mt++) {
            int row = warpM * 32 + mt * 16 + (lane & 7) + ((lane >> 3) & 1) * 8;
            int unit = 2 * ks + (lane >> 4);
            aoff[ks][mt] = row * 64 + (((unit ^ ((row >> 1) & 3)) & 3) << 4);
        }
#pragma unroll
        for (int pair = 0; pair < 2; pair++) {
            int k = ks * 16 + (lane & 7) + ((lane >> 3) & 1) * 8;
            int u = warpN * 4 + pair * 2 + (lane >> 4);
            int su = (u ^ k) & 7;
            boff[ks][pair] = k * 128 + (su << 4);
        }
    }

    float C[8][4];
#pragma unroll
    for (int i = 0; i < 8; i++)
#pragma unroll
        for (int j = 0; j < 4; j++) C[i][j] = 0.f;

    // hoisted load addressing
    int la_m = tid >> 2, la_u = tid & 3;
    const __half* gA = g_Ah + (size_t)(mbase + la_m) * NN + la_u * 8;
    const __half* gA2 = g_Ah + (size_t)(mbase + la_m + 64) * NN + la_u * 8;
    uint32_t sA = la_m * 64 + (((la_u ^ ((la_m >> 1) & 3)) & 3) << 4);
    uint32_t sA2 = (la_m + 64) * 64 + (((la_u ^ (((la_m + 64) >> 1) & 3)) & 3) << 4);
    int lb_k = tid >> 3, lb_u = tid & 7;
    const __half* gB = nin + (size_t)lb_k * CC + cbase + lb_u * 8;
    uint32_t sBo = lb_k * 128 + ((((lb_u ^ lb_k) & 7)) << 4);

    auto load_stage = [&](int ch, int buf) {
        cp16(asb[buf] + sA, gA + ch * 32);
        cp16(asb[buf] + sA2, gA2 + ch * 32);
        cp16(bsb[buf] + sBo, gB + (size_t)ch * 32 * CC);
        asm volatile("cp.async.commit_group;\n" ::: "memory");
    };

    load_stage(0, 0);
    load_stage(1, 1);

    for (int ch = 0; ch < 32; ch++) {
        int buf = ch % 3;
        if (ch + 2 < 32) {
            load_stage(ch + 2, (ch + 2) % 3);
            asm volatile("cp.async.wait_group 2;\n" ::: "memory");
        } else if (ch + 1 < 32) {
            asm volatile("cp.async.wait_group 1;\n" ::: "memory");
        } else {
            asm volatile("cp.async.wait_group 0;\n" ::: "memory");
        }
        __syncthreads();

#pragma unroll
        for (int ks = 0; ks < 2; ks++) {
            uint32_t a[2][4];
#pragma unroll
            for (int mt = 0; mt < 2; mt++) {
                asm volatile("ldmatrix.sync.aligned.m8n8.x4.shared.b16 {%0,%1,%2,%3}, [%4];"
                             : "=r"(a[mt][0]), "=r"(a[mt][1]), "=r"(a[mt][2]), "=r"(a[mt][3])
                             : "r"(asb[buf] + aoff[ks][mt]));
            }
            uint32_t bf[4][2];
#pragma unroll
            for (int pair = 0; pair < 2; pair++) {
                asm volatile("ldmatrix.sync.aligned.m8n8.x4.trans.shared.b16 {%0,%1,%2,%3}, [%4];"
                             : "=r"(bf[pair * 2][0]), "=r"(bf[pair * 2][1]),
                               "=r"(bf[pair * 2 + 1][0]), "=r"(bf[pair * 2 + 1][1])
                             : "r"(bsb[buf] + boff[ks][pair]));
            }
#pragma unroll
            for (int mt = 0; mt < 2; mt++) {
#pragma unroll
                for (int nt = 0; nt < 4; nt++) {
                    float* c = C[mt * 4 + nt];
                    asm volatile(
                        "mma.sync.aligned.m16n8k16.row.col.f32.f16.f16.f32 "
                        "{%0,%1,%2,%3},{%4,%5,%6,%7},{%8,%9},{%0,%1,%2,%3};"
                        : "+f"(c[0]), "+f"(c[1]), "+f"(c[2]), "+f"(c[3])
                        : "r"(a[mt][0]), "r"(a[mt][1]), "r"(a[mt][2]), "r"(a[mt][3]),
                          "r"(bf[nt][0]), "r"(bf[nt][1]));
                }
            }
        }
        __syncthreads();
    }

    int g = lane >> 2, tq = lane & 3;

    if (mode == 0) {
        // ---- epilogue: mu = relu(m13 + pool) into smem; emit next nu (fp16) ----
        float* mt_s = (float*)SB;                 // [128][64] fp32 = 32KB
        float4* W2q = (float4*)(SB + 32768);      // 16KB
        for (int i = tid; i < 1024; i += 256) {
            int d = i >> 4, e4 = i & 15;
            W2q[e4 * 64 + d] = ((const float4*)(W2 + d * DD))[e4];
        }
#pragma unroll
        for (int mt = 0; mt < 2; mt++) {
#pragma unroll
            for (int nt = 0; nt < 4; nt++) {
                const float* c = C[mt * 4 + nt];
                int rl0 = warpM * 32 + mt * 16 + g;
                int cl = warpN * 32 + nt * 8 + tq * 2;
                {
                    const float2 m = *(const float2*)(g_m13 + (size_t)(mbase + rl0) * CC + cbase + cl);
                    mt_s[rl0 * 64 + cl]     = fmaxf(m.x + c[0], 0.f);
                    mt_s[rl0 * 64 + cl + 1] = fmaxf(m.y + c[1], 0.f);
                }
                {
                    int rl1 = rl0 + 8;
                    const float2 m = *(const float2*)(g_m13 + (size_t)(mbase + rl1) * CC + cbase + cl);
                    mt_s[rl1 * 64 + cl]     = fmaxf(m.x + c[2], 0.f);
                    mt_s[rl1 * 64 + cl + 1] = fmaxf(m.y + c[3], 0.f);
                }
            }
        }
        __syncthreads();

        // nu = mu @ W2^T: thread = (rowgroup of 4, dg); acc[4][8]
        int rg = tid >> 3, dg = tid & 7;
        float acc[4][8] = {};
        const float* r0 = mt_s + (rg * 4 + 0) * 64;
        const float* r1 = mt_s + (rg * 4 + 1) * 64;
        const float* r2 = mt_s + (rg * 4 + 2) * 64;
        const float* r3 = mt_s + (rg * 4 + 3) * 64;
#pragma unroll
        for (int e4 = 0; e4 < 16; e4++) {
            float4 m0 = ((const float4*)r0)[e4];
            float4 m1 = ((const float4*)r1)[e4];
            float4 m2 = ((const float4*)r2)[e4];
            float4 m3v = ((const float4*)r3)[e4];
#pragma unroll
            for (int k = 0; k < 8; k++) {
                float4 w = W2q[e4 * 64 + k * 8 + dg];
                acc[0][k] += m0.x * w.x + m0.y * w.y + m0.z * w.z + m0.w * w.w;
                acc[1][k] += m1.x * w.x + m1.y * w.y + m1.z * w.z + m1.w * w.w;
                acc[2][k] += m2.x * w.x + m2.y * w.y + m2.z * w.z + m2.w * w.w;
                acc[3][k] += m3v.x * w.x + m3v.y * w.y + m3v.z * w.z + m3v.w * w.w;
            }
        }
#pragma unroll
        for (int j = 0; j < 4; j++) {
            size_t base = (size_t)(mbase + rg * 4 + j) * CC + cbase + dg;
#pragma unroll
            for (int k = 0; k < 8; k++)
                nout[base + k * 8] = __float2half(acc[j][k]);
        }
    } else {
        // ---- final round: mu -> global, plus column-sum partials ----
#pragma unroll
        for (int mt = 0; mt < 2; mt++) {
#pragma unroll
            for (int nt = 0; nt < 4; nt++) {
                const float* c = C[mt * 4 + nt];
                int row0 = mbase + warpM * 32 + mt * 16 + g;
                int col = cbase + warpN * 32 + nt * 8 + tq * 2;
                {
                    const float2 m = *(const float2*)(g_m13 + (size_t)row0 * CC + col);
                    float2 o;
                    o.x = fmaxf(m.x + c[0], 0.f);
                    o.y = fmaxf(m.y + c[1], 0.f);
                    *(float2*)(g_mu + (size_t)row0 * CC + col) = o;
                }
                {
                    int row1 = row0 + 8;
                    const float2 m = *(const float2*)(g_m13 + (size_t)row1 * CC + col);
                    float2 o;
                    o.x = fmaxf(m.x + c[2], 0.f);
                    o.y = fmaxf(m.y + c[3], 0.f);
                    *(float2*)(g_mu + (size_t)row1 * CC + col) = o;
                }
            }
        }
        float* cs = (float*)SB;
        __syncthreads();
        int c = tid & 63, q = tid >> 6;
        const float* mp = g_mu + (size_t)(mbase + q * 32) * CC + cbase + c;
        float s = 0.f;
#pragma unroll 8
        for (int r = 0; r < 32; r++) s += mp[(size_t)r * CC];
        cs[q * 64 + c] = s;
        __syncthreads();
        if (tid < 64)
            g_part[blockIdx.y * CC + cbase + tid] =
                cs[tid] + cs[64 + tid] + cs[128 + tid] + cs[192 + tid];
    }
}

// ---------------- mumean + s2, one block per b ----------------
__global__ __launch_bounds__(64) void k_small(const float* __restrict__ option,
                                              const float* __restrict__ Wq1,
                                              const float* __restrict__ bq1,
                                              const float* __restrict__ Wq2,
                                              const float* __restrict__ bq2,
                                              const float* __restrict__ Wreg) {
    int b = blockIdx.x, d = threadIdx.x;
    __shared__ float msum[DD];
    float s = 0.f;
#pragma unroll
    for (int g = 0; g < 8; g++) s += g_part[g * CC + b * DD + d];
    msum[d] = s * (1.0f / (float)NN);
    __syncthreads();
    float acc = bq1[d];
#pragma unroll
    for (int e = 0; e < DD; e++) acc += msum[e] * Wq1[d * DD + e];
    g_mumean[b * DD + d] = fmaxf(acc, 0.f);
    float opt = option[b];
    float acc2 = 0.f;
#pragma unroll
    for (int j = 0; j < DD; j++)
        acc2 += (opt * Wq2[j] + bq2[j]) * Wreg[d * (2 * DD) + DD + j];
    g_s2[b * HH + d] = acc2;
}

// ---------------- final head (float4 LDS) ----------------
__global__ __launch_bounds__(256) void k_final(const float* __restrict__ Wreg,
                                               const float* __restrict__ breg,
                                               const float* __restrict__ Wq,
                                               const float* __restrict__ bq,
                                               float* __restrict__ out) {
    int b = blockIdx.y;
    int tile = blockIdx.x;
    __shared__ float Wr[HH][DD + 4];   // 272B stride: float4-aligned, conflict-free
    __shared__ float wqs[HH], s2s[HH], brs[HH];
    __shared__ float vs[8][DD];
    int tid = threadIdx.x;
    for (int i = tid; i < HH * DD; i += 256) {
        int h = i >> 6, j = i & 63;
        Wr[h][j] = Wreg[h * (2 * DD) + j];
    }
    if (tid < HH) {
        wqs[tid] = Wq[tid];
        s2s[tid] = g_s2[b * HH + tid];
        brs[tid] = breg[tid];
    }
    __syncthreads();
    int w = tid >> 5, lane = tid & 31;
    float bqv = bq[0];
    for (int s = 0; s < 8; s++) {
        int i = tile * 64 + w * 8 + s;
        if (i > NN) continue;
        const float* vptr = (i < NN) ? (g_mu + (size_t)i * CC + b * DD) : (g_mumean + b * DD);
        vs[w][lane]      = vptr[lane];
        vs[w][lane + 32] = vptr[lane + 32];
        __syncwarp();
        float r = 0.f;
        const float4* v4 = (const float4*)vs[w];
#pragma unroll
        for (int hh = 0; hh < 2; hh++) {
            int h = lane + hh * 32;
            float accd = s2s[h] + brs[h];
            const float4* w4 = (const float4*)Wr[h];
#pragma unroll
            for (int e = 0; e < 16; e++) {
                float4 vv = v4[e];
                float4 ww = w4[e];
                accd += vv.x * ww.x + vv.y * ww.y + vv.z * ww.z + vv.w * ww.w;
            }
            r += fmaxf(accd, 0.f) * wqs[h];
        }
#pragma unroll
        for (int off = 16; off; off >>= 1) r += __shfl_down_sync(0xffffffff, r, off);
        if (lane == 0) out[b * NP1 + i] = r + bqv;
        __syncwarp();
    }
}

// ---------------- launch ----------------
extern "C" void kernel_launch(void* const* d_in, const int* in_sizes, int n_in,
                              void* d_out, int out_size) {
    const float* xv     = (const float*)d_in[0];
    const float* option = (const float*)d_in[1];
    const float* adj    = (const float*)d_in[2];
    const float* mu1w   = (const float*)d_in[3];
    const float* W2     = (const float*)d_in[4];
    const float* b2     = (const float*)d_in[5];
    const float* W3     = (const float*)d_in[6];
    const float* b3     = (const float*)d_in[7];
    const float* W4     = (const float*)d_in[8];
    const float* b4     = (const float*)d_in[9];
    const float* Wq1    = (const float*)d_in[10];
    const float* bq1    = (const float*)d_in[11];
    const float* Wq2    = (const float*)d_in[12];
    const float* bq2    = (const float*)d_in[13];
    const float* Wreg   = (const float*)d_in[14];
    const float* breg   = (const float*)d_in[15];
    const float* Wq     = (const float*)d_in[16];
    const float* bq     = (const float*)d_in[17];
    float* out = (float*)d_out;
    (void)in_sizes; (void)n_in; (void)out_size;

    static __half *nuA = nullptr, *nuB = nullptr;
    if (!nuA) {
        cudaGetSymbolAddress((void**)&nuA, g_nuA);
        cudaGetSymbolAddress((void**)&nuB, g_nuB);
    }

    k_init<<<NN, 256>>>(adj, W4, b4, W3, b3, xv, mu1w, b2, W2);
    k_mma<<<dim3(CC / 64, NN / 128), 256>>>(0, W2, nuA, nuB);     // t=1: A->B
    k_mma<<<dim3(CC / 64, NN / 128), 256>>>(0, W2, nuB, nuA);     // t=2: B->A
    k_mma<<<dim3(CC / 64, NN / 128), 256>>>(1, W2, nuA, nullptr); // t=3
    k_small<<<32, 64>>>(option, Wq1, bq1, Wq2, bq2, Wreg);
    k_final<<<dim3(17, BB), 256>>>(Wreg, breg, Wq, bq, out);
}

// round 14
// speedup vs baseline: 1.7922x; 1.0510x over previous
#include <cuda_runtime.h>
#include <cuda_fp16.h>
#include <cstdint>

#define NN 1024
#define BB 32
#define FF 32
#define DD 64
#define HH 64
#define CC 2048   // B*D
#define NP1 1025

// ---------------- scratch (static __device__, no allocs) ----------------
__device__ __half g_Ah[NN * NN];      // binarized adjacency, fp16 (exact 0/1)
__device__ float g_m13[NN * CC];      // mu_1 + mu3 + b2
__device__ float g_mu[NN * CC];       // final-round mu (fp32)
__device__ __half g_nuA[NN * CC];     // nu ping buffer (fp16)
__device__ __half g_nuB[NN * CC];     // nu pong buffer (fp16)
__device__ float g_part[8 * CC];      // column-sum partials (per 128-row mtile)
__device__ float g_mumean[BB * DD];
__device__ float g_s2[BB * HH];

// ---------------- helpers ----------------
__device__ __forceinline__ uint32_t smem_u32(const void* p) {
    uint32_t a;
    asm("{ .reg .u64 t; cvta.to.shared.u64 t, %1; cvt.u32.u64 %0, t; }" : "=r"(a) : "l"(p));
    return a;
}
__device__ __forceinline__ void cp16(uint32_t saddr, const void* gaddr) {
    asm volatile("cp.async.cg.shared.global [%0], [%1], 16;\n" :: "r"(saddr), "l"(gaddr));
}

// ---------------- init: binarize adj + mu3 + mu_1 + m13 + first nu ----------------
__global__ __launch_bounds__(256) void k_init(const float* __restrict__ adj,
                                              const float* __restrict__ W4,
                                              const float* __restrict__ b4,
                                              const float* __restrict__ W3,
                                              const float* __restrict__ b3,
                                              const float* __restrict__ xv,
                                              const float* __restrict__ mu1w,
                                              const float* __restrict__ b2,
                                              const float* __restrict__ W2) {
    int n = blockIdx.x;
    int tid = threadIdx.x;
    __shared__ float arow[NN];
    __shared__ float part[4][DD];
    __shared__ float mu4s[DD];
    __shared__ float xs[BB][FF];
    __shared__ float ws[FF][DD];
    __shared__ float m3[DD];
    __shared__ float mus[CC];
    __shared__ float4 W2q[16 * 64];   // [e4][d]

    {
        float4 v = ((const float4*)(adj + (size_t)n * NN))[tid];
        arow[tid * 4 + 0] = v.x;
        arow[tid * 4 + 1] = v.y;
        arow[tid * 4 + 2] = v.z;
        arow[tid * 4 + 3] = v.w;
        union { uint2 u; __half h[4]; } pk;
        pk.h[0] = __float2half(v.x > 0.f ? 1.f : 0.f);
        pk.h[1] = __float2half(v.y > 0.f ? 1.f : 0.f);
        pk.h[2] = __float2half(v.z > 0.f ? 1.f : 0.f);
        pk.h[3] = __float2half(v.w > 0.f ? 1.f : 0.f);
        *(uint2*)(g_Ah + (size_t)n * NN + tid * 4) = pk.u;
    }
    for (int i = tid; i < BB * FF; i += 256) {
        int b = i / FF, f = i % FF;
        xs[b][f] = xv[(b * NN + n) * FF + f];
    }
    for (int i = tid; i < FF * DD; i += 256) ws[i / DD][i % DD] = mu1w[i];
    for (int i = tid; i < 1024; i += 256) {
        int d = i >> 4, e4 = i & 15;
        W2q[e4 * 64 + d] = ((const float4*)(W2 + d * DD))[e4];
    }
    __syncthreads();

    {
        int d = tid & 63, q = tid >> 6;
        float w = W4[d], c0 = b4[d];
        float a0 = 0.f, a1 = 0.f, a2 = 0.f, a3 = 0.f;
        for (int m = q; m < NN; m += 16) {
            a0 += fmaxf(arow[m]      * w + c0, 0.f);
            a1 += fmaxf(arow[m + 4]  * w + c0, 0.f);
            a2 += fmaxf(arow[m + 8]  * w + c0, 0.f);
            a3 += fmaxf(arow[m + 12] * w + c0, 0.f);
        }
        part[q][d] = (a0 + a1) + (a2 + a3);
    }
    __syncthreads();
    if (tid < DD) mu4s[tid] = part[0][tid] + part[1][tid] + part[2][tid] + part[3][tid];
    __syncthreads();
    {
        int d2 = tid & 63, q2 = tid >> 6;
        float a = 0.f;
#pragma unroll
        for (int e = 0; e < 16; e++)
            a += mu4s[q2 * 16 + e] * W3[d2 * DD + q2 * 16 + e];
        part[q2][d2] = a;
    }
    __syncthreads();
    if (tid < DD)
        m3[tid] = b3[tid] + b2[tid] + part[0][tid] + part[1][tid] + part[2][tid] + part[3][tid];
    __syncthreads();

#pragma unroll
    for (int j = 0; j < 8; j++) {
        int c = tid + 256 * j;
        int b = c >> 6, d = c & 63;
        float acc = 0.f;
#pragma unroll
        for (int f = 0; f < FF; f++) acc += xs[b][f] * ws[f][d];
        float r = fmaxf(acc, 0.f);
        g_m13[n * CC + c] = r + m3[d];
        mus[c] = r;
    }
    __syncthreads();

    int b = tid >> 3, dg = tid & 7;
    const float4* mb = (const float4*)(mus + b * DD);
    float acc[8] = {};
#pragma unroll
    for (int e4 = 0; e4 < 16; e4++) {
        float4 m = mb[e4];
#pragma unroll
        for (int k = 0; k < 8; k++) {
            float4 w = W2q[e4 * 64 + k * 8 + dg];
            acc[k] += m.x * w.x + m.y * w.y + m.z * w.z + m.w * w.w;
        }
    }
    size_t base = (size_t)n * CC + b * DD + dg;
#pragma unroll
    for (int k = 0; k < 8; k++)
        g_nuA[base + k * 8] = __float2half(acc[k]);
}

// ---------------- pool = A @ nu via mma.sync fp16; 3-stage cp.async pipeline ----------------
// CTA tile 128(m) x 64(c). 8 warps (4Mx2N), 2 CTAs/SM.
// mode 0: epilogue computes mu (hi/lo fp16 smem) and emits next nu via tensor-core
//         MMA with hi/lo operand splits (hh + hl + lh) -> ~fp32 operand precision.
// mode 1: epilogue writes g_mu + column-sum partials (final round).
__global__ __launch_bounds__(256, 2) void k_mma(int mode, const float* __restrict__ W2,
                                                const __half* __restrict__ nin,
                                                __half* __restrict__ nout) {
    __shared__ __align__(16) char SB[49152];  // stages: 3 x 12KB at 0/12288/24576

    int tid = threadIdx.x;
    int lane = tid & 31, wid = tid >> 5;
    int warpM = wid >> 1, warpN = wid & 1;   // 4 x 2 warps; warp tile 32(m) x 32(c)
    int mbase = blockIdx.y * 128;
    int cbase = blockIdx.x * 64;

    uint32_t sb0 = smem_u32(SB);
    uint32_t asb[3] = { sb0, sb0 + 12288, sb0 + 24576 };         // A: 8KB
    uint32_t bsb[3] = { sb0 + 8192, sb0 + 20480, sb0 + 32768 };  // B: 4KB

    // hoisted ldmatrix offsets (loop-invariant swizzle math)
    uint32_t aoff[2][2], boff[2][2];
#pragma unroll
    for (int ks = 0; ks < 2; ks++) {
#pragma unroll
        for (int mt = 0; mt < 2; mt++) {
            int row = warpM * 32 + mt * 16 + (lane & 7) + ((lane >> 3) & 1) * 8;
            int unit = 2 * ks + (lane >> 4);
            aoff[ks][mt] = row * 64 + (((unit ^ ((row >> 1) & 3)) & 3) << 4);
        }
#pragma unroll
        for (int pair = 0; pair < 2; pair++) {
            int k = ks * 16 + (lane & 7) + ((lane >> 3) & 1) * 8;
            int u = warpN * 4 + pair * 2 + (lane >> 4);
            int su = (u ^ k) & 7;
            boff[ks][pair] = k * 128 + (su << 4);
        }
    }

    float C[8][4];
#pragma unroll
    for (int i = 0; i < 8; i++)
#pragma unroll
        for (int j = 0; j < 4; j++) C[i][j] = 0.f;

    // hoisted load addressing
    int la_m = tid >> 2, la_u = tid & 3;
    const __half* gA = g_Ah + (size_t)(mbase + la_m) * NN + la_u * 8;
    const __half* gA2 = g_Ah + (size_t)(mbase + la_m + 64) * NN + la_u * 8;
    uint32_t sA = la_m * 64 + (((la_u ^ ((la_m >> 1) & 3)) & 3) << 4);
    uint32_t sA2 = (la_m + 64) * 64 + (((la_u ^ (((la_m + 64) >> 1) & 3)) & 3) << 4);
    int lb_k = tid >> 3, lb_u = tid & 7;
    const __half* gB = nin + (size_t)lb_k * CC + cbase + lb_u * 8;
    uint32_t sBo = lb_k * 128 + ((((lb_u ^ lb_k) & 7)) << 4);

    auto load_stage = [&](int ch, int buf) {
        cp16(asb[buf] + sA, gA + ch * 32);
        cp16(asb[buf] + sA2, gA2 + ch * 32);
        cp16(bsb[buf] + sBo, gB + (size_t)ch * 32 * CC);
        asm volatile("cp.async.commit_group;\n" ::: "memory");
    };

    load_stage(0, 0);
    load_stage(1, 1);

    for (int ch = 0; ch < 32; ch++) {
        int buf = ch % 3;
        if (ch + 2 < 32) {
            load_stage(ch + 2, (ch + 2) % 3);
            asm volatile("cp.async.wait_group 2;\n" ::: "memory");
        } else if (ch + 1 < 32) {
            asm volatile("cp.async.wait_group 1;\n" ::: "memory");
        } else {
            asm volatile("cp.async.wait_group 0;\n" ::: "memory");
        }
        __syncthreads();

#pragma unroll
        for (int ks = 0; ks < 2; ks++) {
            uint32_t a[2][4];
#pragma unroll
            for (int mt = 0; mt < 2; mt++) {
                asm volatile("ldmatrix.sync.aligned.m8n8.x4.shared.b16 {%0,%1,%2,%3}, [%4];"
                             : "=r"(a[mt][0]), "=r"(a[mt][1]), "=r"(a[mt][2]), "=r"(a[mt][3])
                             : "r"(asb[buf] + aoff[ks][mt]));
            }
            uint32_t bf[4][2];
#pragma unroll
            for (int pair = 0; pair < 2; pair++) {
                asm volatile("ldmatrix.sync.aligned.m8n8.x4.trans.shared.b16 {%0,%1,%2,%3}, [%4];"
                             : "=r"(bf[pair * 2][0]), "=r"(bf[pair * 2][1]),
                               "=r"(bf[pair * 2 + 1][0]), "=r"(bf[pair * 2 + 1][1])
                             : "r"(bsb[buf] + boff[ks][pair]));
            }
#pragma unroll
            for (int mt = 0; mt < 2; mt++) {
#pragma unroll
                for (int nt = 0; nt < 4; nt++) {
                    float* c = C[mt * 4 + nt];
                    asm volatile(
                        "mma.sync.aligned.m16n8k16.row.col.f32.f16.f16.f32 "
                        "{%0,%1,%2,%3},{%4,%5,%6,%7},{%8,%9},{%0,%1,%2,%3};"
                        : "+f"(c[0]), "+f"(c[1]), "+f"(c[2]), "+f"(c[3])
                        : "r"(a[mt][0]), "r"(a[mt][1]), "r"(a[mt][2]), "r"(a[mt][3]),
                          "r"(bf[nt][0]), "r"(bf[nt][1]));
                }
            }
        }
        __syncthreads();
    }

    int g = lane >> 2, tq = lane & 3;

    if (mode == 0) {
        // ---- epilogue: mu = relu(m13 + pool) -> hi/lo fp16 smem; nu via MMA ----
        // muh [128][64] hi @0 (16KB), mul lo @16384 (16KB),
        // w2h hi @32768 (8KB), w2l lo @40960 (8KB). Swizzle: su = (u ^ (row&7))&7.
        char* muh = (char*)SB;
        char* mul = (char*)SB + 16384;
        char* w2h = (char*)SB + 32768;
        char* w2l = (char*)SB + 40960;
        // stage W2 hi/lo (coalesced global read)
        for (int i = tid; i < 1024; i += 256) {
            int d = i >> 4, e4 = i & 15;
            float4 w = ((const float4*)(W2 + d * DD))[e4];
            int u = e4 >> 1;
            int su = (u ^ (d & 7)) & 7;
            uint32_t off = d * 128 + su * 16 + (e4 & 1) * 8;
            __half hx = __float2half(w.x), hy = __float2half(w.y);
            __half hz = __float2half(w.z), hw = __float2half(w.w);
            union { uint2 u2; __half2 h[2]; } ph, pl;
            ph.h[0] = __halves2half2(hx, hy);
            ph.h[1] = __halves2half2(hz, hw);
            pl.h[0] = __floats2half2_rn(w.x - __half2float(hx), w.y - __half2float(hy));
            pl.h[1] = __floats2half2_rn(w.z - __half2float(hz), w.w - __half2float(hw));
            *(uint2*)(w2h + off) = ph.u2;
            *(uint2*)(w2l + off) = pl.u2;
        }
        // mu tile -> hi/lo fp16 smem
#pragma unroll
        for (int mt = 0; mt < 2; mt++) {
#pragma unroll
            for (int nt = 0; nt < 4; nt++) {
                const float* c = C[mt * 4 + nt];
                int rl0 = warpM * 32 + mt * 16 + g;
                int cl = warpN * 32 + nt * 8 + tq * 2;
                int u = cl >> 3, wo = (cl & 7) * 2;
#pragma unroll
                for (int half = 0; half < 2; half++) {
                    int rl = rl0 + half * 8;
                    const float2 m = *(const float2*)(g_m13 + (size_t)(mbase + rl) * CC + cbase + cl);
                    float vx = fmaxf(m.x + c[half * 2 + 0], 0.f);
                    float vy = fmaxf(m.y + c[half * 2 + 1], 0.f);
                    __half hx = __float2half(vx), hy = __float2half(vy);
                    int su = (u ^ (rl & 7)) & 7;
                    uint32_t off = rl * 128 + su * 16 + wo;
                    *(__half2*)(muh + off) = __halves2half2(hx, hy);
                    *(__half2*)(mul + off) = __floats2half2_rn(vx - __half2float(hx),
                                                               vy - __half2float(hy));
                }
            }
        }
        __syncthreads();

        // per-warp: nu[mrow..mrow+15][0..63] via m16n8k16, hh + hl + lh
        int mrow = wid * 16;
        uint32_t afh[4][4], afl[4][4];
#pragma unroll
        for (int ks = 0; ks < 4; ks++) {
            int row = mrow + (lane & 7) + ((lane >> 3) & 1) * 8;
            int unit = 2 * ks + (lane >> 4);
            int su = (unit ^ (row & 7)) & 7;
            uint32_t off = row * 128 + su * 16;
            asm volatile("ldmatrix.sync.aligned.m8n8.x4.shared.b16 {%0,%1,%2,%3}, [%4];"
                         : "=r"(afh[ks][0]), "=r"(afh[ks][1]), "=r"(afh[ks][2]), "=r"(afh[ks][3])
                         : "r"(sb0 + off));
            asm volatile("ldmatrix.sync.aligned.m8n8.x4.shared.b16 {%0,%1,%2,%3}, [%4];"
                         : "=r"(afl[ks][0]), "=r"(afl[ks][1]), "=r"(afl[ks][2]), "=r"(afl[ks][3])
                         : "r"(sb0 + 16384 + off));
        }
#define NU_MMA(cacc, AH, B0, B1) \
    asm volatile("mma.sync.aligned.m16n8k16.row.col.f32.f16.f16.f32 " \
                 "{%0,%1,%2,%3},{%4,%5,%6,%7},{%8,%9},{%0,%1,%2,%3};" \
                 : "+f"(cacc[0]), "+f"(cacc[1]), "+f"(cacc[2]), "+f"(cacc[3]) \
                 : "r"(AH[0]), "r"(AH[1]), "r"(AH[2]), "r"(AH[3]), "r"(B0), "r"(B1))
#pragma unroll
        for (int pair = 0; pair < 4; pair++) {
            float c0[4] = {}, c1[4] = {};
#pragma unroll
            for (int ks = 0; ks < 4; ks++) {
                int row = pair * 16 + (lane & 7) + ((lane >> 3) & 1) * 8;
                int unit = 2 * ks + (lane >> 4);
                int su = (unit ^ (row & 7)) & 7;
                uint32_t off = row * 128 + su * 16;
                uint32_t bh0, bh1, bh2, bh3, bl0, bl1, bl2, bl3;
                asm volatile("ldmatrix.sync.aligned.m8n8.x4.shared.b16 {%0,%1,%2,%3}, [%4];"
                             : "=r"(bh0), "=r"(bh1), "=r"(bh2), "=r"(bh3) : "r"(sb0 + 32768 + off));
                asm volatile("ldmatrix.sync.aligned.m8n8.x4.shared.b16 {%0,%1,%2,%3}, [%4];"
                             : "=r"(bl0), "=r"(bl1), "=r"(bl2), "=r"(bl3) : "r"(sb0 + 40960 + off));
                NU_MMA(c0, afh[ks], bh0, bh2);
                NU_MMA(c0, afh[ks], bl0, bl2);
                NU_MMA(c0, afl[ks], bh0, bh2);
                NU_MMA(c1, afh[ks], bh1, bh3);
                NU_MMA(c1, afh[ks], bl1, bl3);
                NU_MMA(c1, afl[ks], bh1, bh3);
            }
            size_t grow = (size_t)(mbase + mrow + g);
            int col0 = cbase + pair * 16 + tq * 2;
            *(__half2*)(nout + grow * CC + col0)           = __floats2half2_rn(c0[0], c0[1]);
            *(__half2*)(nout + (grow + 8) * CC + col0)     = __floats2half2_rn(c0[2], c0[3]);
            *(__half2*)(nout + grow * CC + col0 + 8)       = __floats2half2_rn(c1[0], c1[1]);
            *(__half2*)(nout + (grow + 8) * CC + col0 + 8) = __floats2half2_rn(c1[2], c1[3]);
        }
#undef NU_MMA
    } else {
        // ---- final round: mu -> global, plus column-sum partials ----
#pragma unroll
        for (int mt = 0; mt < 2; mt++) {
#pragma unroll
            for (int nt = 0; nt < 4; nt++) {
                const float* c = C[mt * 4 + nt];
                int row0 = mbase + warpM * 32 + mt * 16 + g;
                int col = cbase + warpN * 32 + nt * 8 + tq * 2;
                {
                    const float2 m = *(const float2*)(g_m13 + (size_t)row0 * CC + col);
                    float2 o;
                    o.x = fmaxf(m.x + c[0], 0.f);
                    o.y = fmaxf(m.y + c[1], 0.f);
                    *(float2*)(g_mu + (size_t)row0 * CC + col) = o;
                }
                {
                    int row1 = row0 + 8;
                    const float2 m = *(const float2*)(g_m13 + (size_t)row1 * CC + col);
                    float2 o;
                    o.x = fmaxf(m.x + c[2], 0.f);
                    o.y = fmaxf(m.y + c[3], 0.f);
                    *(float2*)(g_mu + (size_t)row1 * CC + col) = o;
                }
            }
        }
        float* cs = (float*)SB;
        __syncthreads();
        int c = tid & 63, q = tid >> 6;
        const float* mp = g_mu + (size_t)(mbase + q * 32) * CC + cbase + c;
        float s = 0.f;
#pragma unroll 8
        for (int r = 0; r < 32; r++) s += mp[(size_t)r * CC];
        cs[q * 64 + c] = s;
        __syncthreads();
        if (tid < 64)
            g_part[blockIdx.y * CC + cbase + tid] =
                cs[tid] + cs[64 + tid] + cs[128 + tid] + cs[192 + tid];
    }
}

// ---------------- mumean + s2, one block per b ----------------
__global__ __launch_bounds__(64) void k_small(const float* __restrict__ option,
                                              const float* __restrict__ Wq1,
                                              const float* __restrict__ bq1,
                                              const float* __restrict__ Wq2,
                                              const float* __restrict__ bq2,
                                              const float* __restrict__ Wreg) {
    int b = blockIdx.x, d = threadIdx.x;
    __shared__ float msum[DD];
    float s = 0.f;
#pragma unroll
    for (int g = 0; g < 8; g++) s += g_part[g * CC + b * DD + d];
    msum[d] = s * (1.0f / (float)NN);
    __syncthreads();
    float acc = bq1[d];
#pragma unroll
    for (int e = 0; e < DD; e++) acc += msum[e] * Wq1[d * DD + e];
    g_mumean[b * DD + d] = fmaxf(acc, 0.f);
    float opt = option[b];
    float acc2 = 0.f;
#pragma unroll
    for (int j = 0; j < DD; j++)
        acc2 += (opt * Wq2[j] + bq2[j]) * Wreg[d * (2 * DD) + DD + j];
    g_s2[b * HH + d] = acc2;
}

// ---------------- final head (float4 LDS) ----------------
__global__ __launch_bounds__(256) void k_final(const float* __restrict__ Wreg,
                                               const float* __restrict__ breg,
                                               const float* __restrict__ Wq,
                                               const float* __restrict__ bq,
                                               float* __restrict__ out) {
    int b = blockIdx.y;
    int tile = blockIdx.x;
    __shared__ float Wr[HH][DD + 4];   // 272B stride: float4-aligned, conflict-free
    __shared__ float wqs[HH], s2s[HH], brs[HH];
    __shared__ float vs[8][DD];
    int tid = threadIdx.x;
    for (int i = tid; i < HH * DD; i += 256) {
        int h = i >> 6, j = i & 63;
        Wr[h][j] = Wreg[h * (2 * DD) + j];
    }
    if (tid < HH) {
        wqs[tid] = Wq[tid];
        s2s[tid] = g_s2[b * HH + tid];
        brs[tid] = breg[tid];
    }
    __syncthreads();
    int w = tid >> 5, lane = tid & 31;
    float bqv = bq[0];
    for (int s = 0; s < 8; s++) {
        int i = tile * 64 + w * 8 + s;
        if (i > NN) continue;
        const float* vptr = (i < NN) ? (g_mu + (size_t)i * CC + b * DD) : (g_mumean + b * DD);
        vs[w][lane]      = vptr[lane];
        vs[w][lane + 32] = vptr[lane + 32];
        __syncwarp();
        float r = 0.f;
        const float4* v4 = (const float4*)vs[w];
#pragma unroll
        for (int hh = 0; hh < 2; hh++) {
            int h = lane + hh * 32;
            float accd = s2s[h] + brs[h];
            const float4* w4 = (const float4*)Wr[h];
#pragma unroll
            for (int e = 0; e < 16; e++) {
                float4 vv = v4[e];
                float4 ww = w4[e];
                accd += vv.x * ww.x + vv.y * ww.y + vv.z * ww.z + vv.w * ww.w;
            }
            r += fmaxf(accd, 0.f) * wqs[h];
        }
#pragma unroll
        for (int off = 16; off; off >>= 1) r += __shfl_down_sync(0xffffffff, r, off);
        if (lane == 0) out[b * NP1 + i] = r + bqv;
        __syncwarp();
    }
}

// ---------------- launch ----------------
extern "C" void kernel_launch(void* const* d_in, const int* in_sizes, int n_in,
                              void* d_out, int out_size) {
    const float* xv     = (const float*)d_in[0];
    const float* option = (const float*)d_in[1];
    const float* adj    = (const float*)d_in[2];
    const float* mu1w   = (const float*)d_in[3];
    const float* W2     = (const float*)d_in[4];
    const float* b2     = (const float*)d_in[5];
    const float* W3     = (const float*)d_in[6];
    const float* b3     = (const float*)d_in[7];
    const float* W4     = (const float*)d_in[8];
    const float* b4     = (const float*)d_in[9];
    const float* Wq1    = (const float*)d_in[10];
    const float* bq1    = (const float*)d_in[11];
    const float* Wq2    = (const float*)d_in[12];
    const float* bq2    = (const float*)d_in[13];
    const float* Wreg   = (const float*)d_in[14];
    const float* breg   = (const float*)d_in[15];
    const float* Wq     = (const float*)d_in[16];
    const float* bq     = (const float*)d_in[17];
    float* out = (float*)d_out;
    (void)in_sizes; (void)n_in; (void)out_size;

    static __half *nuA = nullptr, *nuB = nullptr;
    if (!nuA) {
        cudaGetSymbolAddress((void**)&nuA, g_nuA);
        cudaGetSymbolAddress((void**)&nuB, g_nuB);
    }

    k_init<<<NN, 256>>>(adj, W4, b4, W3, b3, xv, mu1w, b2, W2);
    k_mma<<<dim3(CC / 64, NN / 128), 256>>>(0, W2, nuA, nuB);     // t=1: A->B
    k_mma<<<dim3(CC / 64, NN / 128), 256>>>(0, W2, nuB, nuA);     // t=2: B->A
    k_mma<<<dim3(CC / 64, NN / 128), 256>>>(1, W2, nuA, nullptr); // t=3
    k_small<<<32, 64>>>(option, Wq1, bq1, Wq2, bq2, Wreg);
    k_final<<<dim3(17, BB), 256>>>(Wreg, breg, Wq, bq, out);
}

// round 15
// speedup vs baseline: 1.9080x; 1.0646x over previous
#include <cuda_runtime.h>
#include <cuda_fp16.h>
#include <cstdint>

#define NN 1024
#define BB 32
#define FF 32
#define DD 64
#define HH 64
#define CC 2048   // B*D
#define NP1 1025

// ---------------- scratch (static __device__, no allocs) ----------------
__device__ __half g_Ah[NN * NN];      // binarized adjacency, fp16 (exact 0/1)
__device__ float g_m13[NN * CC];      // mu_1 + mu3 + b2
__device__ float g_mu[NN * CC];       // final-round mu (fp32)
__device__ __half g_nuA[NN * CC];     // nu ping buffer (fp16)
__device__ __half g_nuB[NN * CC];     // nu pong buffer (fp16)
__device__ float g_part[8 * CC];      // column-sum partials (per 128-row mtile)
__device__ float g_mumean[BB * DD];
__device__ float g_s2[BB * HH];

// ---------------- helpers ----------------
__device__ __forceinline__ uint32_t smem_u32(const void* p) {
    uint32_t a;
    asm("{ .reg .u64 t; cvta.to.shared.u64 t, %1; cvt.u32.u64 %0, t; }" : "=r"(a) : "l"(p));
    return a;
}
__device__ __forceinline__ void cp16(uint32_t saddr, const void* gaddr) {
    asm volatile("cp.async.cg.shared.global [%0], [%1], 16;\n" :: "r"(saddr), "l"(gaddr));
}

// ---------------- init: binarize adj + mu3 + mu_1 + m13 + first nu ----------------
__global__ __launch_bounds__(256) void k_init(const float* __restrict__ adj,
                                              const float* __restrict__ W4,
                                              const float* __restrict__ b4,
                                              const float* __restrict__ W3,
                                              const float* __restrict__ b3,
                                              const float* __restrict__ xv,
                                              const float* __restrict__ mu1w,
                                              const float* __restrict__ b2,
                                              const float* __restrict__ W2) {
    int n = blockIdx.x;
    int tid = threadIdx.x;
    __shared__ float arow[NN];
    __shared__ float part[4][DD];
    __shared__ float mu4s[DD];
    __shared__ float xs[BB][FF];
    __shared__ float ws[FF][DD];
    __shared__ float m3[DD];
    __shared__ float mus[CC];
    __shared__ float4 W2q[16 * 64];   // [e4][d]

    {
        float4 v = ((const float4*)(adj + (size_t)n * NN))[tid];
        arow[tid * 4 + 0] = v.x;
        arow[tid * 4 + 1] = v.y;
        arow[tid * 4 + 2] = v.z;
        arow[tid * 4 + 3] = v.w;
        union { uint2 u; __half h[4]; } pk;
        pk.h[0] = __float2half(v.x > 0.f ? 1.f : 0.f);
        pk.h[1] = __float2half(v.y > 0.f ? 1.f : 0.f);
        pk.h[2] = __float2half(v.z > 0.f ? 1.f : 0.f);
        pk.h[3] = __float2half(v.w > 0.f ? 1.f : 0.f);
        *(uint2*)(g_Ah + (size_t)n * NN + tid * 4) = pk.u;
    }
    for (int i = tid; i < BB * FF; i += 256) {
        int b = i / FF, f = i % FF;
        xs[b][f] = xv[(b * NN + n) * FF + f];
    }
    for (int i = tid; i < FF * DD; i += 256) ws[i / DD][i % DD] = mu1w[i];
    for (int i = tid; i < 1024; i += 256) {
        int d = i >> 4, e4 = i & 15;
        W2q[e4 * 64 + d] = ((const float4*)(W2 + d * DD))[e4];
    }
    __syncthreads();

    {
        int d = tid & 63, q = tid >> 6;
        float w = W4[d], c0 = b4[d];
        float a0 = 0.f, a1 = 0.f, a2 = 0.f, a3 = 0.f;
        for (int m = q; m < NN; m += 16) {
            a0 += fmaxf(arow[m]      * w + c0, 0.f);
            a1 += fmaxf(arow[m + 4]  * w + c0, 0.f);
            a2 += fmaxf(arow[m + 8]  * w + c0, 0.f);
            a3 += fmaxf(arow[m + 12] * w + c0, 0.f);
        }
        part[q][d] = (a0 + a1) + (a2 + a3);
    }
    __syncthreads();
    if (tid < DD) mu4s[tid] = part[0][tid] + part[1][tid] + part[2][tid] + part[3][tid];
    __syncthreads();
    {
        int d2 = tid & 63, q2 = tid >> 6;
        float a = 0.f;
#pragma unroll
        for (int e = 0; e < 16; e++)
            a += mu4s[q2 * 16 + e] * W3[d2 * DD + q2 * 16 + e];
        part[q2][d2] = a;
    }
    __syncthreads();
    if (tid < DD)
        m3[tid] = b3[tid] + b2[tid] + part[0][tid] + part[1][tid] + part[2][tid] + part[3][tid];
    __syncthreads();

#pragma unroll
    for (int j = 0; j < 8; j++) {
        int c = tid + 256 * j;
        int b = c >> 6, d = c & 63;
        float acc = 0.f;
#pragma unroll
        for (int f = 0; f < FF; f++) acc += xs[b][f] * ws[f][d];
        float r = fmaxf(acc, 0.f);
        g_m13[n * CC + c] = r + m3[d];
        mus[c] = r;
    }
    __syncthreads();

    int b = tid >> 3, dg = tid & 7;
    const float4* mb = (const float4*)(mus + b * DD);
    float acc[8] = {};
#pragma unroll
    for (int e4 = 0; e4 < 16; e4++) {
        float4 m = mb[e4];
#pragma unroll
        for (int k = 0; k < 8; k++) {
            float4 w = W2q[e4 * 64 + k * 8 + dg];
            acc[k] += m.x * w.x + m.y * w.y + m.z * w.z + m.w * w.w;
        }
    }
    size_t base = (size_t)n * CC + b * DD + dg;
#pragma unroll
    for (int k = 0; k < 8; k++)
        g_nuA[base + k * 8] = __float2half(acc[k]);
}

// ---------------- pool = A @ nu via mma.sync fp16; 3-stage, 1 barrier/chunk ----------------
// CTA tile 128(m) x 64(c). 8 warps (4Mx2N), 2 CTAs/SM.
// mode 0: epilogue computes mu (hi/lo fp16 smem) and emits next nu via tensor-core
//         MMA with hi/lo operand splits (hh + hl + lh) -> ~fp32 operand precision.
// mode 1: epilogue writes g_mu + column-sum partials (final round).
__global__ __launch_bounds__(256, 2) void k_mma(int mode, const float* __restrict__ W2,
                                                const __half* __restrict__ nin,
                                                __half* __restrict__ nout) {
    __shared__ __align__(16) char SB[49152];  // stages: 3 x 12KB at 0/12288/24576

    int tid = threadIdx.x;
    int lane = tid & 31, wid = tid >> 5;
    int warpM = wid >> 1, warpN = wid & 1;   // 4 x 2 warps; warp tile 32(m) x 32(c)
    int mbase = blockIdx.y * 128;
    int cbase = blockIdx.x * 64;

    uint32_t sb0 = smem_u32(SB);
    uint32_t asb[3] = { sb0, sb0 + 12288, sb0 + 24576 };         // A: 8KB
    uint32_t bsb[3] = { sb0 + 8192, sb0 + 20480, sb0 + 32768 };  // B: 4KB

    // hoisted ldmatrix offsets (loop-invariant swizzle math)
    uint32_t aoff[2][2], boff[2][2];
#pragma unroll
    for (int ks = 0; ks < 2; ks++) {
#pragma unroll
        for (int mt = 0; mt < 2; mt++) {
            int row = warpM * 32 + mt * 16 + (lane & 7) + ((lane >> 3) & 1) * 8;
            int unit = 2 * ks + (lane >> 4);
            aoff[ks][mt] = row * 64 + (((unit ^ ((row >> 1) & 3)) & 3) << 4);
        }
#pragma unroll
        for (int pair = 0; pair < 2; pair++) {
            int k = ks * 16 + (lane & 7) + ((lane >> 3) & 1) * 8;
            int u = warpN * 4 + pair * 2 + (lane >> 4);
            int su = (u ^ k) & 7;
            boff[ks][pair] = k * 128 + (su << 4);
        }
    }

    float C[8][4];
#pragma unroll
    for (int i = 0; i < 8; i++)
#pragma unroll
        for (int j = 0; j < 4; j++) C[i][j] = 0.f;

    // hoisted load addressing
    int la_m = tid >> 2, la_u = tid & 3;
    const __half* gA = g_Ah + (size_t)(mbase + la_m) * NN + la_u * 8;
    const __half* gA2 = g_Ah + (size_t)(mbase + la_m + 64) * NN + la_u * 8;
    uint32_t sA = la_m * 64 + (((la_u ^ ((la_m >> 1) & 3)) & 3) << 4);
    uint32_t sA2 = (la_m + 64) * 64 + (((la_u ^ (((la_m + 64) >> 1) & 3)) & 3) << 4);
    int lb_k = tid >> 3, lb_u = tid & 7;
    const __half* gB = nin + (size_t)lb_k * CC + cbase + lb_u * 8;
    uint32_t sBo = lb_k * 128 + ((((lb_u ^ lb_k) & 7)) << 4);

    auto load_stage = [&](int ch, int buf) {
        cp16(asb[buf] + sA, gA + ch * 32);
        cp16(asb[buf] + sA2, gA2 + ch * 32);
        cp16(bsb[buf] + sBo, gB + (size_t)ch * 32 * CC);
        asm volatile("cp.async.commit_group;\n" ::: "memory");
    };

    load_stage(0, 0);
    load_stage(1, 1);

    for (int ch = 0; ch < 32; ch++) {
        int buf = ch % 3;
        if (ch + 1 < 32) asm volatile("cp.async.wait_group 1;\n" ::: "memory");
        else             asm volatile("cp.async.wait_group 0;\n" ::: "memory");
        __syncthreads();
        // load AFTER the barrier: targets buf (ch+2)%3 == (ch-1)%3, which every
        // thread finished reading (compute of ch-1) before arriving here.
        if (ch + 2 < 32) load_stage(ch + 2, (ch + 2) % 3);

#pragma unroll
        for (int ks = 0; ks < 2; ks++) {
            uint32_t a[2][4];
#pragma unroll
            for (int mt = 0; mt < 2; mt++) {
                asm volatile("ldmatrix.sync.aligned.m8n8.x4.shared.b16 {%0,%1,%2,%3}, [%4];"
                             : "=r"(a[mt][0]), "=r"(a[mt][1]), "=r"(a[mt][2]), "=r"(a[mt][3])
                             : "r"(asb[buf] + aoff[ks][mt]));
            }
            uint32_t bf[4][2];
#pragma unroll
            for (int pair = 0; pair < 2; pair++) {
                asm volatile("ldmatrix.sync.aligned.m8n8.x4.trans.shared.b16 {%0,%1,%2,%3}, [%4];"
                             : "=r"(bf[pair * 2][0]), "=r"(bf[pair * 2][1]),
                               "=r"(bf[pair * 2 + 1][0]), "=r"(bf[pair * 2 + 1][1])
                             : "r"(bsb[buf] + boff[ks][pair]));
            }
#pragma unroll
            for (int mt = 0; mt < 2; mt++) {
#pragma unroll
                for (int nt = 0; nt < 4; nt++) {
                    float* c = C[mt * 4 + nt];
                    asm volatile(
                        "mma.sync.aligned.m16n8k16.row.col.f32.f16.f16.f32 "
                        "{%0,%1,%2,%3},{%4,%5,%6,%7},{%8,%9},{%0,%1,%2,%3};"
                        : "+f"(c[0]), "+f"(c[1]), "+f"(c[2]), "+f"(c[3])
                        : "r"(a[mt][0]), "r"(a[mt][1]), "r"(a[mt][2]), "r"(a[mt][3]),
                          "r"(bf[nt][0]), "r"(bf[nt][1]));
                }
            }
        }
    }
    // protect SB reuse below against warps still reading the last stage buffers
    __syncthreads();

    int g = lane >> 2, tq = lane & 3;

    if (mode == 0) {
        // ---- epilogue: mu = relu(m13 + pool) -> hi/lo fp16 smem; nu via MMA ----
        // muh [128][64] hi @0 (16KB), mul lo @16384 (16KB),
        // w2h hi @32768 (8KB), w2l lo @40960 (8KB). Swizzle: su = (u ^ (row&7))&7.
        char* muh = (char*)SB;
        char* mul = (char*)SB + 16384;
        char* w2h = (char*)SB + 32768;
        char* w2l = (char*)SB + 40960;
        // stage W2 hi/lo (coalesced global read)
        for (int i = tid; i < 1024; i += 256) {
            int d = i >> 4, e4 = i & 15;
            float4 w = ((const float4*)(W2 + d * DD))[e4];
            int u = e4 >> 1;
            int su = (u ^ (d & 7)) & 7;
            uint32_t off = d * 128 + su * 16 + (e4 & 1) * 8;
            __half hx = __float2half(w.x), hy = __float2half(w.y);
            __half hz = __float2half(w.z), hw = __float2half(w.w);
            union { uint2 u2; __half2 h[2]; } ph, pl;
            ph.h[0] = __halves2half2(hx, hy);
            ph.h[1] = __halves2half2(hz, hw);
            pl.h[0] = __floats2half2_rn(w.x - __half2float(hx), w.y - __half2float(hy));
            pl.h[1] = __floats2half2_rn(w.z - __half2float(hz), w.w - __half2float(hw));
            *(uint2*)(w2h + off) = ph.u2;
            *(uint2*)(w2l + off) = pl.u2;
        }
        // mu tile -> hi/lo fp16 smem
#pragma unroll
        for (int mt = 0; mt < 2; mt++) {
#pragma unroll
            for (int nt = 0; nt < 4; nt++) {
                const float* c = C[mt * 4 + nt];
                int rl0 = warpM * 32 + mt * 16 + g;
                int cl = warpN * 32 + nt * 8 + tq * 2;
                int u = cl >> 3, wo = (cl & 7) * 2;
#pragma unroll
                for (int half = 0; half < 2; half++) {
                    int rl = rl0 + half * 8;
                    const float2 m = *(const float2*)(g_m13 + (size_t)(mbase + rl) * CC + cbase + cl);
                    float vx = fmaxf(m.x + c[half * 2 + 0], 0.f);
                    float vy = fmaxf(m.y + c[half * 2 + 1], 0.f);
                    __half hx = __float2half(vx), hy = __float2half(vy);
                    int su = (u ^ (rl & 7)) & 7;
                    uint32_t off = rl * 128 + su * 16 + wo;
                    *(__half2*)(muh + off) = __halves2half2(hx, hy);
                    *(__half2*)(mul + off) = __floats2half2_rn(vx - __half2float(hx),
                                                               vy - __half2float(hy));
                }
            }
        }
        __syncthreads();

        // per-warp: nu[mrow..mrow+15][0..63] via m16n8k16, hh + hl + lh
        int mrow = wid * 16;
        uint32_t afh[4][4], afl[4][4];
#pragma unroll
        for (int ks = 0; ks < 4; ks++) {
            int row = mrow + (lane & 7) + ((lane >> 3) & 1) * 8;
            int unit = 2 * ks + (lane >> 4);
            int su = (unit ^ (row & 7)) & 7;
            uint32_t off = row * 128 + su * 16;
            asm volatile("ldmatrix.sync.aligned.m8n8.x4.shared.b16 {%0,%1,%2,%3}, [%4];"
                         : "=r"(afh[ks][0]), "=r"(afh[ks][1]), "=r"(afh[ks][2]), "=r"(afh[ks][3])
                         : "r"(sb0 + off));
            asm volatile("ldmatrix.sync.aligned.m8n8.x4.shared.b16 {%0,%1,%2,%3}, [%4];"
                         : "=r"(afl[ks][0]), "=r"(afl[ks][1]), "=r"(afl[ks][2]), "=r"(afl[ks][3])
                         : "r"(sb0 + 16384 + off));
        }
#define NU_MMA(cacc, AH, B0, B1) \
    asm volatile("mma.sync.aligned.m16n8k16.row.col.f32.f16.f16.f32 " \
                 "{%0,%1,%2,%3},{%4,%5,%6,%7},{%8,%9},{%0,%1,%2,%3};" \
                 : "+f"(cacc[0]), "+f"(cacc[1]), "+f"(cacc[2]), "+f"(cacc[3]) \
                 : "r"(AH[0]), "r"(AH[1]), "r"(AH[2]), "r"(AH[3]), "r"(B0), "r"(B1))
#pragma unroll
        for (int pair = 0; pair < 4; pair++) {
            float c0[4] = {}, c1[4] = {};
#pragma unroll
            for (int ks = 0; ks < 4; ks++) {
                int row = pair * 16 + (lane & 7) + ((lane >> 3) & 1) * 8;
                int unit = 2 * ks + (lane >> 4);
                int su = (unit ^ (row & 7)) & 7;
                uint32_t off = row * 128 + su * 16;
                uint32_t bh0, bh1, bh2, bh3, bl0, bl1, bl2, bl3;
                asm volatile("ldmatrix.sync.aligned.m8n8.x4.shared.b16 {%0,%1,%2,%3}, [%4];"
                             : "=r"(bh0), "=r"(bh1), "=r"(bh2), "=r"(bh3) : "r"(sb0 + 32768 + off));
                asm volatile("ldmatrix.sync.aligned.m8n8.x4.shared.b16 {%0,%1,%2,%3}, [%4];"
                             : "=r"(bl0), "=r"(bl1), "=r"(bl2), "=r"(bl3) : "r"(sb0 + 40960 + off));
                NU_MMA(c0, afh[ks], bh0, bh2);
                NU_MMA(c0, afh[ks], bl0, bl2);
                NU_MMA(c0, afl[ks], bh0, bh2);
                NU_MMA(c1, afh[ks], bh1, bh3);
                NU_MMA(c1, afh[ks], bl1, bl3);
                NU_MMA(c1, afl[ks], bh1, bh3);
            }
            size_t grow = (size_t)(mbase + mrow + g);
            int col0 = cbase + pair * 16 + tq * 2;
            *(__half2*)(nout + grow * CC + col0)           = __floats2half2_rn(c0[0], c0[1]);
            *(__half2*)(nout + (grow + 8) * CC + col0)     = __floats2half2_rn(c0[2], c0[3]);
            *(__half2*)(nout + grow * CC + col0 + 8)       = __floats2half2_rn(c1[0], c1[1]);
            *(__half2*)(nout + (grow + 8) * CC + col0 + 8) = __floats2half2_rn(c1[2], c1[3]);
        }
#undef NU_MMA
    } else {
        // ---- final round: mu -> global, plus column-sum partials ----
#pragma unroll
        for (int mt = 0; mt < 2; mt++) {
#pragma unroll
            for (int nt = 0; nt < 4; nt++) {
                const float* c = C[mt * 4 + nt];
                int row0 = mbase + warpM * 32 + mt * 16 + g;
                int col = cbase + warpN * 32 + nt * 8 + tq * 2;
                {
                    const float2 m = *(const float2*)(g_m13 + (size_t)row0 * CC + col);
                    float2 o;
                    o.x = fmaxf(m.x + c[0], 0.f);
                    o.y = fmaxf(m.y + c[1], 0.f);
                    *(float2*)(g_mu + (size_t)row0 * CC + col) = o;
                }
                {
                    int row1 = row0 + 8;
                    const float2 m = *(const float2*)(g_m13 + (size_t)row1 * CC + col);
                    float2 o;
                    o.x = fmaxf(m.x + c[2], 0.f);
                    o.y = fmaxf(m.y + c[3], 0.f);
                    *(float2*)(g_mu + (size_t)row1 * CC + col) = o;
                }
            }
        }
        float* cs = (float*)SB;
        __syncthreads();
        int c = tid & 63, q = tid >> 6;
        const float* mp = g_mu + (size_t)(mbase + q * 32) * CC + cbase + c;
        float s = 0.f;
#pragma unroll 8
        for (int r = 0; r < 32; r++) s += mp[(size_t)r * CC];
        cs[q * 64 + c] = s;
        __syncthreads();
        if (tid < 64)
            g_part[blockIdx.y * CC + cbase + tid] =
                cs[tid] + cs[64 + tid] + cs[128 + tid] + cs[192 + tid];
    }
}

// ---------------- mumean + s2, one block per b ----------------
__global__ __launch_bounds__(64) void k_small(const float* __restrict__ option,
                                              const float* __restrict__ Wq1,
                                              const float* __restrict__ bq1,
                                              const float* __restrict__ Wq2,
                                              const float* __restrict__ bq2,
                                              const float* __restrict__ Wreg) {
    int b = blockIdx.x, d = threadIdx.x;
    __shared__ float msum[DD];
    float s = 0.f;
#pragma unroll
    for (int g = 0; g < 8; g++) s += g_part[g * CC + b * DD + d];
    msum[d] = s * (1.0f / (float)NN);
    __syncthreads();
    float acc = bq1[d];
#pragma unroll
    for (int e = 0; e < DD; e++) acc += msum[e] * Wq1[d * DD + e];
    g_mumean[b * DD + d] = fmaxf(acc, 0.f);
    float opt = option[b];
    float acc2 = 0.f;
#pragma unroll
    for (int j = 0; j < DD; j++)
        acc2 += (opt * Wq2[j] + bq2[j]) * Wreg[d * (2 * DD) + DD + j];
    g_s2[b * HH + d] = acc2;
}

// ---------------- final head (float4 LDS) ----------------
__global__ __launch_bounds__(256) void k_final(const float* __restrict__ Wreg,
                                               const float* __restrict__ breg,
                                               const float* __restrict__ Wq,
                                               const float* __restrict__ bq,
                                               float* __restrict__ out) {
    int b = blockIdx.y;
    int tile = blockIdx.x;
    __shared__ float Wr[HH][DD + 4];   // 272B stride: float4-aligned, conflict-free
    __shared__ float wqs[HH], s2s[HH], brs[HH];
    __shared__ float vs[8][DD];
    int tid = threadIdx.x;
    for (int i = tid; i < HH * DD; i += 256) {
        int h = i >> 6, j = i & 63;
        Wr[h][j] = Wreg[h * (2 * DD) + j];
    }
    if (tid < HH) {
        wqs[tid] = Wq[tid];
        s2s[tid] = g_s2[b * HH + tid];
        brs[tid] = breg[tid];
    }
    __syncthreads();
    int w = tid >> 5, lane = tid & 31;
    float bqv = bq[0];
    for (int s = 0; s < 8; s++) {
        int i = tile * 64 + w * 8 + s;
        if (i > NN) continue;
        const float* vptr = (i < NN) ? (g_mu + (size_t)i * CC + b * DD) : (g_mumean + b * DD);
        vs[w][lane]      = vptr[lane];
        vs[w][lane + 32] = vptr[lane + 32];
        __syncwarp();
        float r = 0.f;
        const float4* v4 = (const float4*)vs[w];
#pragma unroll
        for (int hh = 0; hh < 2; hh++) {
            int h = lane + hh * 32;
            float accd = s2s[h] + brs[h];
            const float4* w4 = (const float4*)Wr[h];
#pragma unroll
            for (int e = 0; e < 16; e++) {
                float4 vv = v4[e];
                float4 ww = w4[e];
                accd += vv.x * ww.x + vv.y * ww.y + vv.z * ww.z + vv.w * ww.w;
            }
            r += fmaxf(accd, 0.f) * wqs[h];
        }
#pragma unroll
        for (int off = 16; off; off >>= 1) r += __shfl_down_sync(0xffffffff, r, off);
        if (lane == 0) out[b * NP1 + i] = r + bqv;
        __syncwarp();
    }
}

// ---------------- launch ----------------
extern "C" void kernel_launch(void* const* d_in, const int* in_sizes, int n_in,
                              void* d_out, int out_size) {
    const float* xv     = (const float*)d_in[0];
    const float* option = (const float*)d_in[1];
    const float* adj    = (const float*)d_in[2];
    const float* mu1w   = (const float*)d_in[3];
    const float* W2     = (const float*)d_in[4];
    const float* b2     = (const float*)d_in[5];
    const float* W3     = (const float*)d_in[6];
    const float* b3     = (const float*)d_in[7];
    const float* W4     = (const float*)d_in[8];
    const float* b4     = (const float*)d_in[9];
    const float* Wq1    = (const float*)d_in[10];
    const float* bq1    = (const float*)d_in[11];
    const float* Wq2    = (const float*)d_in[12];
    const float* bq2    = (const float*)d_in[13];
    const float* Wreg   = (const float*)d_in[14];
    const float* breg   = (const float*)d_in[15];
    const float* Wq     = (const float*)d_in[16];
    const float* bq     = (const float*)d_in[17];
    float* out = (float*)d_out;
    (void)in_sizes; (void)n_in; (void)out_size;

    static __half *nuA = nullptr, *nuB = nullptr;
    if (!nuA) {
        cudaGetSymbolAddress((void**)&nuA, g_nuA);
        cudaGetSymbolAddress((void**)&nuB, g_nuB);
    }

    k_init<<<NN, 256>>>(adj, W4, b4, W3, b3, xv, mu1w, b2, W2);
    k_mma<<<dim3(CC / 64, NN / 128), 256>>>(0, W2, nuA, nuB);     // t=1: A->B
    k_mma<<<dim3(CC / 64, NN / 128), 256>>>(0, W2, nuB, nuA);     // t=2: B->A
    k_mma<<<dim3(CC / 64, NN / 128), 256>>>(1, W2, nuA, nullptr); // t=3
    k_small<<<32, 64>>>(option, Wq1, bq1, Wq2, bq2, Wreg);
    k_final<<<dim3(17, BB), 256>>>(Wreg, breg, Wq, bq, out);
}